// round 1
// baseline (speedup 1.0000x reference)
#include <cuda_runtime.h>
#include <math.h>

// ---------------------------------------------------------------------------
// Problem constants
// ---------------------------------------------------------------------------
#define BATCH 32
#define NV    512          // V (global tokens)
#define NQ    512          // Q (local tokens)
#define GD    512
#define LD    256
#define DIM   384          // transformer width
#define TH    3            // self-attn heads
#define THD   32           // self-attn head dim
#define HOUT  4            // cross-attn heads
#define DH    96           // cross-attn head dim
#define HID   128
#define ROWS  (BATCH * NV) // 16384 (both streams have 512 tokens)

// ---------------------------------------------------------------------------
// Scratch (__device__ globals; allocation-free per harness rules)
// ---------------------------------------------------------------------------
__device__ float g_ga[ROWS * DIM];        // global stream activations (in-place through transformer)
__device__ float g_la[ROWS * DIM];        // local stream activations
__device__ float g_h[ROWS * DIM];         // LN output scratch
__device__ float g_qkv[ROWS * 288];       // qkv projection
__device__ float g_dots[96 * 512 * 512];  // self-attn dots (B*TH batches)
__device__ float g_attnout[ROWS * 96];    // self-attn output (pre-Wo)
__device__ float g_ff[ROWS * 128];        // FF hidden
__device__ float g_qh[ROWS * DIM];        // cross q
__device__ float g_kh[ROWS * DIM];        // cross k
__device__ float g_u[128 * 512 * 384];    // u[b,h,v,d] = scores @ la
__device__ float g_logits[128 * 384];     // logits per (b,h)
__device__ int   g_mask[ROWS];            // mask per (b,v)

// ---------------------------------------------------------------------------
// Generic tiled GEMM: C = act(A @ W + bias) (+ residual)
// A: [M,K] row-major, W: [K,N] row-major. Batched via blockIdx.z:
//   A += z*sA, C += z*sC (res too), W += (z/wdiv)*sW
// ACT: 0 none, 1 relu, 2 gelu(exact)
// ---------------------------------------------------------------------------
template<int ACT, bool RES>
__global__ void gemm_k(const float* __restrict__ A, const float* __restrict__ W,
                       const float* __restrict__ bias, const float* __restrict__ res,
                       float* __restrict__ C, int M, int N, int K,
                       long long sA, long long sW, long long sC, int wdiv)
{
    int z = blockIdx.z;
    A += (long long)z * sA;
    C += (long long)z * sC;
    W += (long long)(z / wdiv) * sW;
    if (RES) res += (long long)z * sC;

    __shared__ float As[16][65];
    __shared__ float Ws[16][64];

    int m0 = blockIdx.y * 64, n0 = blockIdx.x * 64;
    int tid = threadIdx.x;
    int tx = tid & 15, ty = tid >> 4;

    float acc[4][4] = {};

    for (int k0 = 0; k0 < K; k0 += 16) {
        // Load A tile [64 m][16 k] (K divisible by 16 in all uses; M divisible by 64)
        #pragma unroll
        for (int i = 0; i < 4; i++) {
            int ml = (tid >> 4) + 16 * i;
            int kl = tid & 15;
            As[kl][ml] = A[(long long)(m0 + ml) * K + (k0 + kl)];
        }
        // Load W tile [16 k][64 n]  (guard N; N=288 case not divisible by 64)
        #pragma unroll
        for (int i = 0; i < 4; i++) {
            int kl = (tid >> 6) + 4 * i;
            int nl = tid & 63;
            int n = n0 + nl;
            Ws[kl][nl] = (n < N) ? W[(long long)(k0 + kl) * N + n] : 0.f;
        }
        __syncthreads();
        #pragma unroll
        for (int k = 0; k < 16; k++) {
            float a[4], b[4];
            #pragma unroll
            for (int r = 0; r < 4; r++) a[r] = As[k][(ty << 2) + r];
            #pragma unroll
            for (int c = 0; c < 4; c++) b[c] = Ws[k][(tx << 2) + c];
            #pragma unroll
            for (int r = 0; r < 4; r++)
                #pragma unroll
                for (int c = 0; c < 4; c++)
                    acc[r][c] += a[r] * b[c];
        }
        __syncthreads();
    }

    #pragma unroll
    for (int r = 0; r < 4; r++) {
        int m = m0 + (ty << 2) + r;
        #pragma unroll
        for (int c = 0; c < 4; c++) {
            int n = n0 + (tx << 2) + c;
            if (n >= N) continue;
            float v = acc[r][c];
            if (bias) v += bias[n];
            if (ACT == 1) v = fmaxf(v, 0.f);
            if (ACT == 2) v = 0.5f * v * (1.f + erff(v * 0.70710678118654752f));
            if (RES) v += res[(long long)m * N + n];
            C[(long long)m * N + n] = v;
        }
    }
}

// ---------------------------------------------------------------------------
// LayerNorm over rows of 384, block=128 threads (3 elems/thread)
// ---------------------------------------------------------------------------
__global__ void layernorm_k(const float* __restrict__ x, const float* __restrict__ g,
                            const float* __restrict__ b, float* __restrict__ y)
{
    long long row = blockIdx.x;
    const float* xr = x + row * DIM;
    float* yr = y + row * DIM;
    int t = threadIdx.x;

    float v[3], s = 0.f, s2 = 0.f;
    #pragma unroll
    for (int i = 0; i < 3; i++) {
        v[i] = xr[t + 128 * i];
        s += v[i];
        s2 += v[i] * v[i];
    }
    __shared__ float sa[128], sb[128];
    sa[t] = s; sb[t] = s2;
    __syncthreads();
    for (int st = 64; st > 0; st >>= 1) {
        if (t < st) { sa[t] += sa[t + st]; sb[t] += sb[t + st]; }
        __syncthreads();
    }
    float mean = sa[0] * (1.f / DIM);
    float var = sb[0] * (1.f / DIM) - mean * mean;
    float rstd = rsqrtf(var + 1e-5f);
    #pragma unroll
    for (int i = 0; i < 3; i++) {
        int d = t + 128 * i;
        yr[d] = (v[i] - mean) * rstd * g[d] + b[d];
    }
}

// ---------------------------------------------------------------------------
// Self-attn dots: dots[bh][i][j] = (q_i . k_j) / sqrt(32)
// grid (jTile=8, iTile=8, bh=96), 256 threads
// ---------------------------------------------------------------------------
__global__ void attn_dots_k(const float* __restrict__ qkv, float* __restrict__ dots)
{
    int bh = blockIdx.z;
    int b = bh / TH, h = bh % TH;
    const float* base = qkv + (long long)b * 512 * 288;
    int i0 = blockIdx.y * 64, j0 = blockIdx.x * 64;

    __shared__ float qs[32][65];
    __shared__ float ks[32][65];
    int tid = threadIdx.x;

    for (int e = tid; e < 2048; e += 256) {
        int r = e >> 5, d = e & 31;
        qs[d][r] = base[(long long)(i0 + r) * 288 + h * 32 + d];
        ks[d][r] = base[(long long)(j0 + r) * 288 + 96 + h * 32 + d];
    }
    __syncthreads();

    int tx = tid & 15, ty = tid >> 4;
    float acc[4][4] = {};
    #pragma unroll
    for (int d = 0; d < 32; d++) {
        float a[4], bb[4];
        #pragma unroll
        for (int r = 0; r < 4; r++) a[r] = qs[d][(ty << 2) + r];
        #pragma unroll
        for (int c = 0; c < 4; c++) bb[c] = ks[d][(tx << 2) + c];
        #pragma unroll
        for (int r = 0; r < 4; r++)
            #pragma unroll
            for (int c = 0; c < 4; c++)
                acc[r][c] += a[r] * bb[c];
    }
    const float scale = 0.1767766952966369f; // 1/sqrt(32)
    float* out = dots + (long long)bh * 512 * 512;
    #pragma unroll
    for (int r = 0; r < 4; r++)
        #pragma unroll
        for (int c = 0; c < 4; c++)
            out[(long long)(i0 + (ty << 2) + r) * 512 + j0 + (tx << 2) + c] = acc[r][c] * scale;
}

// ---------------------------------------------------------------------------
// Row softmax over 512 elems; one block (256 thr) per row
// ---------------------------------------------------------------------------
__global__ void softmax_k(float* __restrict__ x)
{
    float* row = x + (long long)blockIdx.x * 512;
    int t = threadIdx.x;
    float v0 = row[t], v1 = row[t + 256];
    __shared__ float sh[256];
    sh[t] = fmaxf(v0, v1);
    __syncthreads();
    for (int s = 128; s > 0; s >>= 1) {
        if (t < s) sh[t] = fmaxf(sh[t], sh[t + s]);
        __syncthreads();
    }
    float m = sh[0];
    __syncthreads();
    float e0 = expf(v0 - m), e1 = expf(v1 - m);
    sh[t] = e0 + e1;
    __syncthreads();
    for (int s = 128; s > 0; s >>= 1) {
        if (t < s) sh[t] += sh[t + s];
        __syncthreads();
    }
    float inv = 1.f / sh[0];
    row[t] = e0 * inv;
    row[t + 256] = e1 * inv;
}

// ---------------------------------------------------------------------------
// attn @ V: out[bh][i][d] = sum_j attn[i][j] * v[j][d]  (512x512 @ 512x32)
// grid (iTile=8, bh=96), 256 threads: lane d = tid&31, group ig = tid>>5 (8 rows strided)
// ---------------------------------------------------------------------------
__global__ void attn_v_k(const float* __restrict__ dots, const float* __restrict__ qkv,
                         float* __restrict__ out)
{
    int bh = blockIdx.y;
    int b = bh / TH, h = bh % TH;
    int i0 = blockIdx.x * 64;
    const float* attn = dots + (long long)bh * 512 * 512;
    const float* vbase = qkv + (long long)b * 512 * 288 + 192 + h * 32;

    __shared__ float as[64][64];
    __shared__ float vs[64][32];
    int tid = threadIdx.x;
    int d = tid & 31, ig = tid >> 5;
    float acc[8] = {};

    for (int j0 = 0; j0 < 512; j0 += 64) {
        for (int e = tid; e < 4096; e += 256) {
            int r = e >> 6, c = e & 63;
            as[r][c] = attn[(long long)(i0 + r) * 512 + j0 + c];
        }
        for (int e = tid; e < 2048; e += 256) {
            int r = e >> 5, c = e & 31;
            vs[r][c] = vbase[(long long)(j0 + r) * 288 + c];
        }
        __syncthreads();
        #pragma unroll 8
        for (int j = 0; j < 64; j++) {
            float vv = vs[j][d];
            #pragma unroll
            for (int r = 0; r < 8; r++) acc[r] += as[ig + 8 * r][j] * vv;
        }
        __syncthreads();
    }
    float* ob = out + (long long)(b * 512 + i0) * 96 + h * 32 + d;
    #pragma unroll
    for (int r = 0; r < 8; r++) ob[(long long)(ig + 8 * r) * 96] = acc[r];
}

// ---------------------------------------------------------------------------
// mask[b*V+v] = (sum_g |global_feat[b,v,g]| == 0)   — one warp per row
// ---------------------------------------------------------------------------
__global__ void mask_k(const float* __restrict__ gf, int* __restrict__ mask)
{
    int gw = (blockIdx.x * blockDim.x + threadIdx.x) >> 5;
    int lane = threadIdx.x & 31;
    if (gw >= ROWS) return;
    const float* row = gf + (long long)gw * GD;
    float s = 0.f;
    for (int i = lane; i < GD; i += 32) s += fabsf(row[i]);
    #pragma unroll
    for (int o = 16; o > 0; o >>= 1) s += __shfl_down_sync(0xffffffffu, s, o);
    if (lane == 0) mask[gw] = (s == 0.0f) ? 1 : 0;
}

// ---------------------------------------------------------------------------
// Cross scores: scores[b,h,v,q] = mask[b,v] ? 0 : (qh_v . kh_q)/sqrt(96) + bias[h]
// grid (qTile=8, vTile=8, bh=128), 256 threads, K=96 in two 48-chunks
// ---------------------------------------------------------------------------
__global__ void cross_scores_k(const float* __restrict__ qh, const float* __restrict__ kh,
                               const float* __restrict__ att_bias, const int* __restrict__ mask,
                               float* __restrict__ scores)
{
    int bh = blockIdx.z;
    int b = bh >> 2, h = bh & 3;
    int v0 = blockIdx.y * 64, q0 = blockIdx.x * 64;
    const float* qb = qh + (long long)b * 512 * DIM + h * DH;
    const float* kb = kh + (long long)b * 512 * DIM + h * DH;

    __shared__ float qs[48][65];
    __shared__ float ks[48][65];
    int tid = threadIdx.x;
    int tx = tid & 15, ty = tid >> 4;
    float acc[4][4] = {};

    for (int dc = 0; dc < DH; dc += 48) {
        for (int e = tid; e < 64 * 48; e += 256) {
            int r = e / 48, d = e % 48;
            qs[d][r] = qb[(long long)(v0 + r) * DIM + dc + d];
            ks[d][r] = kb[(long long)(q0 + r) * DIM + dc + d];
        }
        __syncthreads();
        #pragma unroll
        for (int d = 0; d < 48; d++) {
            float a[4], bb[4];
            #pragma unroll
            for (int r = 0; r < 4; r++) a[r] = qs[d][(ty << 2) + r];
            #pragma unroll
            for (int c = 0; c < 4; c++) bb[c] = ks[d][(tx << 2) + c];
            #pragma unroll
            for (int r = 0; r < 4; r++)
                #pragma unroll
                for (int c = 0; c < 4; c++)
                    acc[r][c] += a[r] * bb[c];
        }
        __syncthreads();
    }
    const float scale = 0.10206207261596575f; // 1/sqrt(96)
    float bias = att_bias[h];
    #pragma unroll
    for (int r = 0; r < 4; r++) {
        int v = v0 + (ty << 2) + r;
        bool m = (mask[b * 512 + v] != 0);
        #pragma unroll
        for (int c = 0; c < 4; c++) {
            int q = q0 + (tx << 2) + c;
            float val = m ? 0.f : (acc[r][c] * scale + bias);
            scores[((long long)bh * 512 + v) * 512 + q] = val;
        }
    }
}

// ---------------------------------------------------------------------------
// logits[b,h,d] = sum_v ga[b,v,d] * u[b,h,v,d]  — grid 128, 384 threads
// ---------------------------------------------------------------------------
__global__ void logits_k(const float* __restrict__ ga, const float* __restrict__ u,
                         float* __restrict__ logits)
{
    int bh = blockIdx.x;
    int b = bh >> 2;
    int d = threadIdx.x;
    const float* gp = ga + (long long)b * 512 * DIM + d;
    const float* up = u + (long long)bh * 512 * DIM + d;
    float acc = 0.f;
    for (int v = 0; v < 512; v++) acc += gp[(long long)v * DIM] * up[(long long)v * DIM];
    logits[bh * DIM + d] = acc;
}

// ---------------------------------------------------------------------------
// Final: sum over h, pool triples, BN (eval), dot with Wf + bf
// grid 32 (=B), 128 threads (=HID)
// ---------------------------------------------------------------------------
__global__ void final_k(const float* __restrict__ logits,
                        const float* __restrict__ bn_g, const float* __restrict__ bn_b,
                        const float* __restrict__ bn_mean, const float* __restrict__ bn_var,
                        const float* __restrict__ Wf, const float* __restrict__ bf,
                        float* __restrict__ out)
{
    int b = blockIdx.x, t = threadIdx.x;
    float pooled = 0.f;
    #pragma unroll
    for (int h = 0; h < 4; h++) {
        const float* lp = logits + (b * 4 + h) * DIM + t * 3;
        pooled += lp[0] + lp[1] + lp[2];
    }
    float bn = (pooled - bn_mean[t]) * rsqrtf(bn_var[t] + 1e-5f) * bn_g[t] + bn_b[t];
    __shared__ float sh[128];
    sh[t] = bn * Wf[t];
    __syncthreads();
    for (int s = 64; s > 0; s >>= 1) {
        if (t < s) sh[t] += sh[t + s];
        __syncthreads();
    }
    if (t == 0) out[b] = sh[0] + bf[0];
}

// ---------------------------------------------------------------------------
// Host side
// ---------------------------------------------------------------------------
struct TrWeights {
    const float *ln1_g, *ln1_b, *Wqkv, *Wo, *bo, *ln2_g, *ln2_b, *W1, *b1, *W2, *b2;
};

static void run_transformer(float* x, float* h, float* qkv, float* dots, float* attnout,
                            float* ff, const TrWeights& w)
{
    layernorm_k<<<ROWS, 128>>>(x, w.ln1_g, w.ln1_b, h);
    gemm_k<0, false><<<dim3(5, 256, 1), 256>>>(h, w.Wqkv, nullptr, nullptr, qkv,
                                               ROWS, 288, 384, 0, 0, 0, 1);
    attn_dots_k<<<dim3(8, 8, 96), 256>>>(qkv, dots);
    softmax_k<<<96 * 512, 256>>>(dots);
    attn_v_k<<<dim3(8, 96), 256>>>(dots, qkv, attnout);
    gemm_k<0, true><<<dim3(6, 256, 1), 256>>>(attnout, w.Wo, w.bo, x, x,
                                              ROWS, 384, 96, 0, 0, 0, 1);
    layernorm_k<<<ROWS, 128>>>(x, w.ln2_g, w.ln2_b, h);
    gemm_k<2, false><<<dim3(2, 256, 1), 256>>>(h, w.W1, w.b1, nullptr, ff,
                                               ROWS, 128, 384, 0, 0, 0, 1);
    gemm_k<0, true><<<dim3(6, 256, 1), 256>>>(ff, w.W2, w.b2, x, x,
                                              ROWS, 384, 128, 0, 0, 0, 1);
}

extern "C" void kernel_launch(void* const* d_in, const int* in_sizes, int n_in,
                              void* d_out, int out_size)
{
    // Inputs (metadata order)
    const float* global_feat = (const float*)d_in[0];
    const float* local_feat  = (const float*)d_in[1];
    const float* Wg   = (const float*)d_in[2];
    const float* bg   = (const float*)d_in[3];
    const float* Wl   = (const float*)d_in[4];
    const float* bl   = (const float*)d_in[5];
    TrWeights tw;
    tw.ln1_g = (const float*)d_in[6];
    tw.ln1_b = (const float*)d_in[7];
    tw.Wqkv  = (const float*)d_in[8];
    tw.Wo    = (const float*)d_in[9];
    tw.bo    = (const float*)d_in[10];
    tw.ln2_g = (const float*)d_in[11];
    tw.ln2_b = (const float*)d_in[12];
    tw.W1    = (const float*)d_in[13];
    tw.b1    = (const float*)d_in[14];
    tw.W2    = (const float*)d_in[15];
    tw.b2    = (const float*)d_in[16];
    const float* Wq       = (const float*)d_in[17];
    const float* Wk       = (const float*)d_in[18];
    const float* att_bias = (const float*)d_in[19];
    const float* bn_g     = (const float*)d_in[20];
    const float* bn_b     = (const float*)d_in[21];
    const float* bn_mean  = (const float*)d_in[22];
    const float* bn_var   = (const float*)d_in[23];
    const float* Wf       = (const float*)d_in[24];
    const float* bf       = (const float*)d_in[25];

    // Scratch pointers
    void *p;
    cudaGetSymbolAddress(&p, g_ga);      float* ga      = (float*)p;
    cudaGetSymbolAddress(&p, g_la);      float* la      = (float*)p;
    cudaGetSymbolAddress(&p, g_h);       float* hbuf    = (float*)p;
    cudaGetSymbolAddress(&p, g_qkv);     float* qkv     = (float*)p;
    cudaGetSymbolAddress(&p, g_dots);    float* dots    = (float*)p;
    cudaGetSymbolAddress(&p, g_attnout); float* attnout = (float*)p;
    cudaGetSymbolAddress(&p, g_ff);      float* ff      = (float*)p;
    cudaGetSymbolAddress(&p, g_qh);      float* qh      = (float*)p;
    cudaGetSymbolAddress(&p, g_kh);      float* kh      = (float*)p;
    cudaGetSymbolAddress(&p, g_u);       float* u       = (float*)p;
    cudaGetSymbolAddress(&p, g_logits);  float* logits  = (float*)p;
    cudaGetSymbolAddress(&p, g_mask);    int*   mask    = (int*)p;

    // Output layout: tuple (out [B,1], scores [B,4,512,512]) flattened in order
    float* out_scalar = (float*)d_out;
    float* scores = out_scalar + BATCH;

    // 1) Input projections with ReLU
    gemm_k<1, false><<<dim3(6, 256, 1), 256>>>(global_feat, Wg, bg, nullptr, ga,
                                               ROWS, DIM, GD, 0, 0, 0, 1);
    gemm_k<1, false><<<dim3(6, 256, 1), 256>>>(local_feat, Wl, bl, nullptr, la,
                                               ROWS, DIM, LD, 0, 0, 0, 1);

    // 2) Shared-weight transformer on both streams
    run_transformer(ga, hbuf, qkv, dots, attnout, ff, tw);
    run_transformer(la, hbuf, qkv, dots, attnout, ff, tw);

    // 3) Cross-attention q/k projections
    gemm_k<0, false><<<dim3(6, 256, 1), 256>>>(ga, Wq, nullptr, nullptr, qh,
                                               ROWS, DIM, DIM, 0, 0, 0, 1);
    gemm_k<0, false><<<dim3(6, 256, 1), 256>>>(la, Wk, nullptr, nullptr, kh,
                                               ROWS, DIM, DIM, 0, 0, 0, 1);

    // 4) Mask + scores (written directly into d_out)
    mask_k<<<(ROWS * 32 + 255) / 256, 256>>>(global_feat, mask);
    cross_scores_k<<<dim3(8, 8, 128), 256>>>(qh, kh, att_bias, mask, scores);

    // 5) u[bh] = scores[bh] (512x512) @ la[b] (512x384) — 128-batch GEMM
    gemm_k<0, false><<<dim3(6, 8, 128), 256>>>(scores, la, nullptr, nullptr, u,
                                               512, 384, 512,
                                               512LL * 512, 512LL * 384, 512LL * 384, 4);

    // 6) logits + head
    logits_k<<<128, 384>>>(ga, u, logits);
    final_k<<<BATCH, 128>>>(logits, bn_g, bn_b, bn_mean, bn_var, Wf, bf, out_scalar);
}

// round 2
// speedup vs baseline: 1.1034x; 1.1034x over previous
#include <cuda_runtime.h>
#include <math.h>

// ---------------------------------------------------------------------------
// Problem constants
// ---------------------------------------------------------------------------
#define BATCH 32
#define GD    512
#define LD    256
#define DIM   384
#define TH    3
#define THD   32
#define HOUT  4
#define DH    96
#define HID   128
#define ROWS  (BATCH * 512)   // 16384

// ---------------------------------------------------------------------------
// Scratch
// ---------------------------------------------------------------------------
__device__ float g_ga[ROWS * DIM];
__device__ float g_la[ROWS * DIM];
__device__ float g_h[ROWS * DIM];
__device__ float g_qkv[ROWS * 288];
__device__ float g_attnout[ROWS * 96];
__device__ float g_ff[ROWS * 128];
__device__ float g_qh[ROWS * DIM];
__device__ float g_kh[ROWS * DIM];
__device__ float g_u[128 * 512 * 384];
__device__ float g_logits[128 * 384];
__device__ int   g_mask[ROWS];

// ---------------------------------------------------------------------------
// 128x128x8 register-blocked GEMM: C = act(A @ W + bias) (+ residual)
// A: [M,K] row-major (lda=K), W: [K,N] row-major (ldw=N).
// Batched via blockIdx.z: A += z*sA, C += z*sC, W += (z/wdiv)*sW.
// Requires: M % 128 == 0, K % 8 == 0, K % 4 == 0 for float4 A loads.
// N guarded (handles N=288).
// ACT: 0 none, 1 relu, 2 gelu(exact)
// ---------------------------------------------------------------------------
template<int ACT, bool RES>
__global__ __launch_bounds__(256, 2)
void gemm128(const float* __restrict__ A, const float* __restrict__ W,
             const float* __restrict__ bias, const float* __restrict__ res,
             float* __restrict__ C, int M, int N, int K,
             long long sA, long long sW, long long sC, int wdiv)
{
    int z = blockIdx.z;
    A += (long long)z * sA;
    C += (long long)z * sC;
    W += (long long)(z / wdiv) * sW;
    const float* Rp = RES ? (res + (long long)z * sC) : nullptr;

    __shared__ float As[8][132];   // padded: conflict-free transpose store
    __shared__ float Ws[8][128];

    int m0 = blockIdx.y * 128, n0 = blockIdx.x * 128;
    int tid = threadIdx.x;
    int arow = tid >> 1, akq = (tid & 1) * 4;       // A: 128 rows x 8 k
    int wk = tid >> 5, wn = (tid & 31) * 4;         // W: 8 k x 128 n
    bool nfull = (n0 + 128 <= N);

    int tx = tid & 15, ty = tid >> 4;
    float acc[8][8] = {};

    const float* Aptr = A + (long long)(m0 + arow) * K + akq;
    const float* Wptr = W + (long long)wk * N + n0 + wn;

    float4 areg = *(const float4*)Aptr;
    float4 wreg;
    if (nfull) {
        wreg = *(const float4*)Wptr;
    } else {
        wreg.x = (n0 + wn     < N) ? Wptr[0] : 0.f;
        wreg.y = (n0 + wn + 1 < N) ? Wptr[1] : 0.f;
        wreg.z = (n0 + wn + 2 < N) ? Wptr[2] : 0.f;
        wreg.w = (n0 + wn + 3 < N) ? Wptr[3] : 0.f;
    }

    for (int k0 = 0; k0 < K; k0 += 8) {
        As[akq + 0][arow] = areg.x;
        As[akq + 1][arow] = areg.y;
        As[akq + 2][arow] = areg.z;
        As[akq + 3][arow] = areg.w;
        *(float4*)&Ws[wk][wn] = wreg;
        __syncthreads();

        bool more = (k0 + 8 < K);
        if (more) {
            Aptr += 8;
            areg = *(const float4*)Aptr;
            Wptr += (long long)8 * N;
            if (nfull) {
                wreg = *(const float4*)Wptr;
            } else {
                wreg.x = (n0 + wn     < N) ? Wptr[0] : 0.f;
                wreg.y = (n0 + wn + 1 < N) ? Wptr[1] : 0.f;
                wreg.z = (n0 + wn + 2 < N) ? Wptr[2] : 0.f;
                wreg.w = (n0 + wn + 3 < N) ? Wptr[3] : 0.f;
            }
        }

        #pragma unroll
        for (int k = 0; k < 8; k++) {
            float a[8], b[8];
            *(float4*)(a)     = *(const float4*)&As[k][ty * 8];
            *(float4*)(a + 4) = *(const float4*)&As[k][ty * 8 + 4];
            *(float4*)(b)     = *(const float4*)&Ws[k][tx * 8];
            *(float4*)(b + 4) = *(const float4*)&Ws[k][tx * 8 + 4];
            #pragma unroll
            for (int r = 0; r < 8; r++)
                #pragma unroll
                for (int c = 0; c < 8; c++)
                    acc[r][c] += a[r] * b[c];
        }
        __syncthreads();
    }

    #pragma unroll
    for (int r = 0; r < 8; r++) {
        long long m = m0 + ty * 8 + r;
        #pragma unroll
        for (int c = 0; c < 8; c++) {
            int n = n0 + tx * 8 + c;
            if (n >= N) continue;
            float v = acc[r][c];
            if (bias) v += bias[n];
            if (ACT == 1) v = fmaxf(v, 0.f);
            if (ACT == 2) v = 0.5f * v * (1.f + erff(v * 0.70710678118654752f));
            if (RES) v += Rp[m * N + n];
            C[m * N + n] = v;
        }
    }
}

// ---------------------------------------------------------------------------
// Cross scores: scores[b,h,v,q] = mask[b,v] ? 0 : (qh_v . kh_q)/sqrt(96)+bias[h]
// 128x128 tiles, K=96, A/B row stride 384. grid (4,4,128)
// ---------------------------------------------------------------------------
__global__ __launch_bounds__(256, 2)
void cross_scores128(const float* __restrict__ qh, const float* __restrict__ kh,
                     const float* __restrict__ att_bias, const int* __restrict__ mask,
                     float* __restrict__ scores)
{
    int bh = blockIdx.z;
    int b = bh >> 2, h = bh & 3;
    const float* Ab = qh + (long long)b * 512 * DIM + h * DH;   // [v][k], ld=384
    const float* Bb = kh + (long long)b * 512 * DIM + h * DH;   // [q][k], ld=384

    __shared__ float As[8][132];
    __shared__ float Bs[8][132];

    int v0 = blockIdx.y * 128, q0 = blockIdx.x * 128;
    int tid = threadIdx.x;
    int arow = tid >> 1, akq = (tid & 1) * 4;

    int tx = tid & 15, ty = tid >> 4;
    float acc[8][8] = {};

    const float* Aptr = Ab + (long long)(v0 + arow) * DIM + akq;
    const float* Bptr = Bb + (long long)(q0 + arow) * DIM + akq;
    float4 areg = *(const float4*)Aptr;
    float4 breg = *(const float4*)Bptr;

    for (int k0 = 0; k0 < DH; k0 += 8) {
        As[akq + 0][arow] = areg.x;
        As[akq + 1][arow] = areg.y;
        As[akq + 2][arow] = areg.z;
        As[akq + 3][arow] = areg.w;
        Bs[akq + 0][arow] = breg.x;
        Bs[akq + 1][arow] = breg.y;
        Bs[akq + 2][arow] = breg.z;
        Bs[akq + 3][arow] = breg.w;
        __syncthreads();
        if (k0 + 8 < DH) {
            Aptr += 8; Bptr += 8;
            areg = *(const float4*)Aptr;
            breg = *(const float4*)Bptr;
        }
        #pragma unroll
        for (int k = 0; k < 8; k++) {
            float a[8], bb[8];
            *(float4*)(a)      = *(const float4*)&As[k][ty * 8];
            *(float4*)(a + 4)  = *(const float4*)&As[k][ty * 8 + 4];
            *(float4*)(bb)     = *(const float4*)&Bs[k][tx * 8];
            *(float4*)(bb + 4) = *(const float4*)&Bs[k][tx * 8 + 4];
            #pragma unroll
            for (int r = 0; r < 8; r++)
                #pragma unroll
                for (int c = 0; c < 8; c++)
                    acc[r][c] += a[r] * bb[c];
        }
        __syncthreads();
    }

    const float scale = 0.10206207261596575f; // 1/sqrt(96)
    float biash = att_bias[h];
    float* out = scores + (long long)bh * 512 * 512;
    #pragma unroll
    for (int r = 0; r < 8; r++) {
        int v = v0 + ty * 8 + r;
        bool mv = (mask[b * 512 + v] != 0);
        float4 o[2];
        #pragma unroll
        for (int c = 0; c < 8; c++) {
            float val = mv ? 0.f : (acc[r][c] * scale + biash);
            ((float*)o)[c] = val;
        }
        float* row = out + (long long)v * 512 + q0 + tx * 8;
        *(float4*)row = o[0];
        *(float4*)(row + 4) = o[1];
    }
}

// ---------------------------------------------------------------------------
// Flash self-attention: out[b,i,h*32+d] = softmax(QK^T/sqrt(32)) @ V
// One block per (bh, 64 i-rows). 256 threads: row = tid/4, tq = tid%4.
// ---------------------------------------------------------------------------
__global__ __launch_bounds__(256, 2)
void flash_attn_k(const float* __restrict__ qkv, float* __restrict__ out)
{
    int bh = blockIdx.y;
    int b = bh / TH, h = bh % TH;
    int i0 = blockIdx.x * 64;
    const float* base = qkv + (long long)b * 512 * 288;
    const float* qb = base + h * 32;
    const float* kb = base + 96 + h * 32;
    const float* vb = base + 192 + h * 32;

    __shared__ float qs[64][36];
    __shared__ float ks[64][36];
    __shared__ float vs[64][36];
    __shared__ float ps[64][65];

    int tid = threadIdx.x;
    int r = tid >> 2, tq = tid & 3;

    for (int e = tid; e < 512; e += 256) {
        int row = e >> 3, c4 = (e & 7) * 4;
        *(float4*)&qs[row][c4] = *(const float4*)&qb[(long long)(i0 + row) * 288 + c4];
    }
    __syncthreads();
    float q[32];
    #pragma unroll
    for (int i = 0; i < 8; i++) *(float4*)&q[i * 4] = *(const float4*)&qs[r][i * 4];

    float O[8] = {};
    float mrow = -INFINITY, lrow = 0.f;
    const float scale = 0.1767766952966369f; // 1/sqrt(32)

    for (int j0 = 0; j0 < 512; j0 += 64) {
        __syncthreads();
        for (int e = tid; e < 512; e += 256) {
            int row = e >> 3, c4 = (e & 7) * 4;
            *(float4*)&ks[row][c4] = *(const float4*)&kb[(long long)(j0 + row) * 288 + c4];
            *(float4*)&vs[row][c4] = *(const float4*)&vb[(long long)(j0 + row) * 288 + c4];
        }
        __syncthreads();

        float s[16];
        #pragma unroll
        for (int jj = 0; jj < 16; jj++) {
            int j = jj * 4 + tq;
            float a = 0.f;
            #pragma unroll
            for (int d4 = 0; d4 < 8; d4++) {
                float4 kk = *(const float4*)&ks[j][d4 * 4];
                a += q[d4*4+0]*kk.x + q[d4*4+1]*kk.y + q[d4*4+2]*kk.z + q[d4*4+3]*kk.w;
            }
            s[jj] = a * scale;
        }
        float smax = s[0];
        #pragma unroll
        for (int jj = 1; jj < 16; jj++) smax = fmaxf(smax, s[jj]);
        #pragma unroll
        for (int o = 1; o < 4; o <<= 1)
            smax = fmaxf(smax, __shfl_xor_sync(0xffffffffu, smax, o));
        float mnew = fmaxf(mrow, smax);
        float corr = __expf(mrow - mnew);
        float psum = 0.f;
        #pragma unroll
        for (int jj = 0; jj < 16; jj++) {
            float p = __expf(s[jj] - mnew);
            ps[r][jj * 4 + tq] = p;
            psum += p;
        }
        #pragma unroll
        for (int o = 1; o < 4; o <<= 1)
            psum += __shfl_xor_sync(0xffffffffu, psum, o);
        lrow = lrow * corr + psum;
        mrow = mnew;
        #pragma unroll
        for (int d = 0; d < 8; d++) O[d] *= corr;
        __syncwarp();

        int d0 = tq * 8;
        #pragma unroll 8
        for (int j = 0; j < 64; j++) {
            float pj = ps[r][j];
            float4 v0 = *(const float4*)&vs[j][d0];
            float4 v1 = *(const float4*)&vs[j][d0 + 4];
            O[0] += pj * v0.x; O[1] += pj * v0.y; O[2] += pj * v0.z; O[3] += pj * v0.w;
            O[4] += pj * v1.x; O[5] += pj * v1.y; O[6] += pj * v1.z; O[7] += pj * v1.w;
        }
    }

    float inv = 1.f / lrow;
    float* ob = out + (long long)(b * 512 + i0 + r) * 96 + h * 32 + tq * 8;
    float4 o0 = {O[0]*inv, O[1]*inv, O[2]*inv, O[3]*inv};
    float4 o1 = {O[4]*inv, O[5]*inv, O[6]*inv, O[7]*inv};
    *(float4*)ob = o0;
    *(float4*)(ob + 4) = o1;
}

// ---------------------------------------------------------------------------
// LayerNorm (rows of 384)
// ---------------------------------------------------------------------------
__global__ void layernorm_k(const float* __restrict__ x, const float* __restrict__ g,
                            const float* __restrict__ b, float* __restrict__ y)
{
    long long row = blockIdx.x;
    const float* xr = x + row * DIM;
    float* yr = y + row * DIM;
    int t = threadIdx.x;

    float v[3], s = 0.f, s2 = 0.f;
    #pragma unroll
    for (int i = 0; i < 3; i++) {
        v[i] = xr[t + 128 * i];
        s += v[i];
        s2 += v[i] * v[i];
    }
    __shared__ float sa[128], sb[128];
    sa[t] = s; sb[t] = s2;
    __syncthreads();
    for (int st = 64; st > 0; st >>= 1) {
        if (t < st) { sa[t] += sa[t + st]; sb[t] += sb[t + st]; }
        __syncthreads();
    }
    float mean = sa[0] * (1.f / DIM);
    float var = sb[0] * (1.f / DIM) - mean * mean;
    float rstd = rsqrtf(var + 1e-5f);
    #pragma unroll
    for (int i = 0; i < 3; i++) {
        int d = t + 128 * i;
        yr[d] = (v[i] - mean) * rstd * g[d] + b[d];
    }
}

// ---------------------------------------------------------------------------
// mask[b*512+v] = (sum_g |gf[b,v,g]| == 0)  — one warp per row
// ---------------------------------------------------------------------------
__global__ void mask_k(const float* __restrict__ gf, int* __restrict__ mask)
{
    int gw = (blockIdx.x * blockDim.x + threadIdx.x) >> 5;
    int lane = threadIdx.x & 31;
    if (gw >= ROWS) return;
    const float* row = gf + (long long)gw * GD;
    float s = 0.f;
    for (int i = lane; i < GD; i += 32) s += fabsf(row[i]);
    #pragma unroll
    for (int o = 16; o > 0; o >>= 1) s += __shfl_down_sync(0xffffffffu, s, o);
    if (lane == 0) mask[gw] = (s == 0.0f) ? 1 : 0;
}

// ---------------------------------------------------------------------------
// logits[b,h,d] = sum_v ga[b,v,d] * u[b,h,v,d]
// ---------------------------------------------------------------------------
__global__ void logits_k(const float* __restrict__ ga, const float* __restrict__ u,
                         float* __restrict__ logits)
{
    int bh = blockIdx.x;
    int b = bh >> 2;
    int d = threadIdx.x;
    const float* gp = ga + (long long)b * 512 * DIM + d;
    const float* up = u + (long long)bh * 512 * DIM + d;
    float acc = 0.f;
    for (int v = 0; v < 512; v++) acc += gp[(long long)v * DIM] * up[(long long)v * DIM];
    logits[bh * DIM + d] = acc;
}

// ---------------------------------------------------------------------------
// Final head
// ---------------------------------------------------------------------------
__global__ void final_k(const float* __restrict__ logits,
                        const float* __restrict__ bn_g, const float* __restrict__ bn_b,
                        const float* __restrict__ bn_mean, const float* __restrict__ bn_var,
                        const float* __restrict__ Wf, const float* __restrict__ bf,
                        float* __restrict__ out)
{
    int b = blockIdx.x, t = threadIdx.x;
    float pooled = 0.f;
    #pragma unroll
    for (int h = 0; h < 4; h++) {
        const float* lp = logits + (b * 4 + h) * DIM + t * 3;
        pooled += lp[0] + lp[1] + lp[2];
    }
    float bn = (pooled - bn_mean[t]) * rsqrtf(bn_var[t] + 1e-5f) * bn_g[t] + bn_b[t];
    __shared__ float sh[128];
    sh[t] = bn * Wf[t];
    __syncthreads();
    for (int s = 64; s > 0; s >>= 1) {
        if (t < s) sh[t] += sh[t + s];
        __syncthreads();
    }
    if (t == 0) out[b] = sh[0] + bf[0];
}

// ---------------------------------------------------------------------------
// Host side
// ---------------------------------------------------------------------------
struct TrWeights {
    const float *ln1_g, *ln1_b, *Wqkv, *Wo, *bo, *ln2_g, *ln2_b, *W1, *b1, *W2, *b2;
};

static void run_transformer(float* x, float* h, float* qkv, float* attnout,
                            float* ff, const TrWeights& w)
{
    layernorm_k<<<ROWS, 128>>>(x, w.ln1_g, w.ln1_b, h);
    gemm128<0, false><<<dim3(3, 128, 1), 256>>>(h, w.Wqkv, nullptr, nullptr, qkv,
                                                ROWS, 288, 384, 0, 0, 0, 1);
    flash_attn_k<<<dim3(8, 96), 256>>>(qkv, attnout);
    gemm128<0, true><<<dim3(3, 128, 1), 256>>>(attnout, w.Wo, w.bo, x, x,
                                               ROWS, 384, 96, 0, 0, 0, 1);
    layernorm_k<<<ROWS, 128>>>(x, w.ln2_g, w.ln2_b, h);
    gemm128<2, false><<<dim3(1, 128, 1), 256>>>(h, w.W1, w.b1, nullptr, ff,
                                                ROWS, 128, 384, 0, 0, 0, 1);
    gemm128<0, true><<<dim3(3, 128, 1), 256>>>(ff, w.W2, w.b2, x, x,
                                               ROWS, 384, 128, 0, 0, 0, 1);
}

extern "C" void kernel_launch(void* const* d_in, const int* in_sizes, int n_in,
                              void* d_out, int out_size)
{
    const float* global_feat = (const float*)d_in[0];
    const float* local_feat  = (const float*)d_in[1];
    const float* Wg   = (const float*)d_in[2];
    const float* bg   = (const float*)d_in[3];
    const float* Wl   = (const float*)d_in[4];
    const float* bl   = (const float*)d_in[5];
    TrWeights tw;
    tw.ln1_g = (const float*)d_in[6];
    tw.ln1_b = (const float*)d_in[7];
    tw.Wqkv  = (const float*)d_in[8];
    tw.Wo    = (const float*)d_in[9];
    tw.bo    = (const float*)d_in[10];
    tw.ln2_g = (const float*)d_in[11];
    tw.ln2_b = (const float*)d_in[12];
    tw.W1    = (const float*)d_in[13];
    tw.b1    = (const float*)d_in[14];
    tw.W2    = (const float*)d_in[15];
    tw.b2    = (const float*)d_in[16];
    const float* Wq       = (const float*)d_in[17];
    const float* Wk       = (const float*)d_in[18];
    const float* att_bias = (const float*)d_in[19];
    const float* bn_g     = (const float*)d_in[20];
    const float* bn_b     = (const float*)d_in[21];
    const float* bn_mean  = (const float*)d_in[22];
    const float* bn_var   = (const float*)d_in[23];
    const float* Wf       = (const float*)d_in[24];
    const float* bf       = (const float*)d_in[25];

    void *p;
    cudaGetSymbolAddress(&p, g_ga);      float* ga      = (float*)p;
    cudaGetSymbolAddress(&p, g_la);      float* la      = (float*)p;
    cudaGetSymbolAddress(&p, g_h);       float* hbuf    = (float*)p;
    cudaGetSymbolAddress(&p, g_qkv);     float* qkv     = (float*)p;
    cudaGetSymbolAddress(&p, g_attnout); float* attnout = (float*)p;
    cudaGetSymbolAddress(&p, g_ff);      float* ff      = (float*)p;
    cudaGetSymbolAddress(&p, g_qh);      float* qh      = (float*)p;
    cudaGetSymbolAddress(&p, g_kh);      float* kh      = (float*)p;
    cudaGetSymbolAddress(&p, g_u);       float* u       = (float*)p;
    cudaGetSymbolAddress(&p, g_logits);  float* logits  = (float*)p;
    cudaGetSymbolAddress(&p, g_mask);    int*   mask    = (int*)p;

    float* out_scalar = (float*)d_out;
    float* scores = out_scalar + BATCH;

    // 1) Input projections (ReLU)
    gemm128<1, false><<<dim3(3, 128, 1), 256>>>(global_feat, Wg, bg, nullptr, ga,
                                                ROWS, DIM, GD, 0, 0, 0, 1);
    gemm128<1, false><<<dim3(3, 128, 1), 256>>>(local_feat, Wl, bl, nullptr, la,
                                                ROWS, DIM, LD, 0, 0, 0, 1);

    // 2) Shared-weight transformer on both streams
    run_transformer(ga, hbuf, qkv, attnout, ff, tw);
    run_transformer(la, hbuf, qkv, attnout, ff, tw);

    // 3) Cross q/k projections
    gemm128<0, false><<<dim3(3, 128, 1), 256>>>(ga, Wq, nullptr, nullptr, qh,
                                                ROWS, DIM, DIM, 0, 0, 0, 1);
    gemm128<0, false><<<dim3(3, 128, 1), 256>>>(la, Wk, nullptr, nullptr, kh,
                                                ROWS, DIM, DIM, 0, 0, 0, 1);

    // 4) Mask + cross scores (into d_out)
    mask_k<<<(ROWS * 32 + 255) / 256, 256>>>(global_feat, mask);
    cross_scores128<<<dim3(4, 4, 128), 256>>>(qh, kh, att_bias, mask, scores);

    // 5) u[bh] = scores[bh] @ la[b]  (batched, wdiv=4)
    gemm128<0, false><<<dim3(3, 4, 128), 256>>>(scores, la, nullptr, nullptr, u,
                                                512, 384, 512,
                                                512LL * 512, 512LL * 384, 512LL * 384, 4);

    // 6) logits + head
    logits_k<<<128, 384>>>(ga, u, logits);
    final_k<<<BATCH, 128>>>(logits, bn_g, bn_b, bn_mean, bn_var, Wf, bf, out_scalar);
}

// round 3
// speedup vs baseline: 2.0389x; 1.8478x over previous
#include <cuda_runtime.h>
#include <math.h>
#include <stdint.h>

// ---------------------------------------------------------------------------
// Problem constants
// ---------------------------------------------------------------------------
#define BATCH 32
#define GD    512
#define LD    256
#define DIM   384
#define TH    3
#define THD   32
#define HOUT  4
#define DH    96
#define HID   128
#define ROWS  (BATCH * 512)   // 16384

// ---------------------------------------------------------------------------
// Scratch
// ---------------------------------------------------------------------------
__device__ float g_ga[ROWS * DIM];
__device__ float g_la[ROWS * DIM];
__device__ float g_h[ROWS * DIM];
__device__ float g_qkv[ROWS * 288];
__device__ float g_attnout[ROWS * 96];
__device__ float g_ff[ROWS * 128];
__device__ float g_qh[ROWS * DIM];
__device__ float g_kh[ROWS * DIM];
__device__ float g_u[128 * 512 * 384];
__device__ float g_logits[128 * 384];
__device__ int   g_mask[ROWS];

// ---------------------------------------------------------------------------
// TF32 helpers
// ---------------------------------------------------------------------------
__device__ __forceinline__ float to_tf32(float x) {
    uint32_t u;
    asm("cvt.rna.tf32.f32 %0, %1;" : "=r"(u) : "f"(x));
    return __uint_as_float(u);
}

__device__ __forceinline__ void mma_tf32(float* d, const uint32_t* a, const uint32_t* b) {
    asm volatile(
        "mma.sync.aligned.m16n8k8.row.col.f32.tf32.tf32.f32 "
        "{%0,%1,%2,%3}, {%4,%5,%6,%7}, {%8,%9}, {%0,%1,%2,%3};"
        : "+f"(d[0]), "+f"(d[1]), "+f"(d[2]), "+f"(d[3])
        : "r"(a[0]), "r"(a[1]), "r"(a[2]), "r"(a[3]), "r"(b[0]), "r"(b[1]));
}

// ---------------------------------------------------------------------------
// TF32 tensor-core GEMM: C = act(A @ W + bias) (+ residual)
// A: [M,K] row-major, W: [K,N] row-major. 128x128 block tile, BK=16.
// 128 threads = 4 warps in 2x2, each warp 64x64 (4x8 m16n8k8 tiles).
// Batched via blockIdx.z (A += z*sA, C += z*sC, W += (z/wdiv)*sW).
// Requires M%128==0, K%16==0, N%4==0 (N guarded for N=288).
// ---------------------------------------------------------------------------
template<int ACT, bool RES>
__global__ __launch_bounds__(128, 2)
void gemm_tc(const float* __restrict__ A, const float* __restrict__ W,
             const float* __restrict__ bias, const float* __restrict__ res,
             float* __restrict__ C, int M, int N, int K,
             long long sA, long long sW, long long sC, int wdiv)
{
    int z = blockIdx.z;
    A += (long long)z * sA;
    C += (long long)z * sC;
    W += (long long)(z / wdiv) * sW;
    const float* Rp = RES ? (res + (long long)z * sC) : nullptr;

    __shared__ float As[128][20];   // [m][k], stride 20 -> conflict-free frag loads
    __shared__ float Bs[16][136];   // [k][n], stride 136 -> conflict-free frag loads

    int m0 = blockIdx.y * 128, n0 = blockIdx.x * 128;
    int tid = threadIdx.x;
    int warp = tid >> 5, lane = tid & 31;
    int wm = (warp >> 1) * 64, wn = (warp & 1) * 64;

    float acc[4][8][4];
    #pragma unroll
    for (int i = 0; i < 4; i++)
        #pragma unroll
        for (int j = 0; j < 8; j++)
            #pragma unroll
            for (int r = 0; r < 4; r++) acc[i][j][r] = 0.f;

    const float* Ap = A + (long long)(m0 + tid) * K;
    int bk = tid >> 5;                  // 0..3
    int bnq = (tid & 31) * 4;           // 0..124
    const float* Wp = W + (long long)bk * N + n0 + bnq;
    bool nok = (n0 + bnq < N);          // N%4==0 -> full float4 when true

    float4 av[4], bv[4];
    #pragma unroll
    for (int c = 0; c < 4; c++) av[c] = *(const float4*)(Ap + c * 4);
    #pragma unroll
    for (int r = 0; r < 4; r++)
        bv[r] = nok ? *(const float4*)(Wp + (long long)(r * 4) * N)
                    : make_float4(0.f, 0.f, 0.f, 0.f);

    for (int k0 = 0; k0 < K; k0 += 16) {
        #pragma unroll
        for (int c = 0; c < 4; c++) {
            As[tid][c * 4 + 0] = to_tf32(av[c].x);
            As[tid][c * 4 + 1] = to_tf32(av[c].y);
            As[tid][c * 4 + 2] = to_tf32(av[c].z);
            As[tid][c * 4 + 3] = to_tf32(av[c].w);
        }
        #pragma unroll
        for (int r = 0; r < 4; r++) {
            int k = bk + r * 4;
            Bs[k][bnq + 0] = to_tf32(bv[r].x);
            Bs[k][bnq + 1] = to_tf32(bv[r].y);
            Bs[k][bnq + 2] = to_tf32(bv[r].z);
            Bs[k][bnq + 3] = to_tf32(bv[r].w);
        }
        __syncthreads();

        if (k0 + 16 < K) {
            Ap += 16;
            Wp += (long long)16 * N;
            #pragma unroll
            for (int c = 0; c < 4; c++) av[c] = *(const float4*)(Ap + c * 4);
            #pragma unroll
            for (int r = 0; r < 4; r++)
                bv[r] = nok ? *(const float4*)(Wp + (long long)(r * 4) * N)
                            : make_float4(0.f, 0.f, 0.f, 0.f);
        }

        #pragma unroll
        for (int ks = 0; ks < 2; ks++) {
            int ko = ks * 8;
            uint32_t af[4][4], bf[8][2];
            #pragma unroll
            for (int i = 0; i < 4; i++) {
                int mr = wm + i * 16 + (lane >> 2);
                int kc = ko + (lane & 3);
                af[i][0] = __float_as_uint(As[mr][kc]);
                af[i][1] = __float_as_uint(As[mr + 8][kc]);
                af[i][2] = __float_as_uint(As[mr][kc + 4]);
                af[i][3] = __float_as_uint(As[mr + 8][kc + 4]);
            }
            #pragma unroll
            for (int j = 0; j < 8; j++) {
                int nc = wn + j * 8 + (lane >> 2);
                int kr = ko + (lane & 3);
                bf[j][0] = __float_as_uint(Bs[kr][nc]);
                bf[j][1] = __float_as_uint(Bs[kr + 4][nc]);
            }
            #pragma unroll
            for (int i = 0; i < 4; i++)
                #pragma unroll
                for (int j = 0; j < 8; j++)
                    mma_tf32(acc[i][j], af[i], bf[j]);
        }
        __syncthreads();
    }

    // Epilogue
    #pragma unroll
    for (int i = 0; i < 4; i++) {
        long long r0 = m0 + wm + i * 16 + (lane >> 2);
        long long r1 = r0 + 8;
        #pragma unroll
        for (int j = 0; j < 8; j++) {
            int cn = n0 + wn + j * 8 + (lane & 3) * 2;
            if (cn >= N) continue;
            float v00 = acc[i][j][0], v01 = acc[i][j][1];
            float v10 = acc[i][j][2], v11 = acc[i][j][3];
            if (bias) {
                float b0 = bias[cn], b1 = bias[cn + 1];
                v00 += b0; v01 += b1; v10 += b0; v11 += b1;
            }
            if (ACT == 1) {
                v00 = fmaxf(v00, 0.f); v01 = fmaxf(v01, 0.f);
                v10 = fmaxf(v10, 0.f); v11 = fmaxf(v11, 0.f);
            }
            if (ACT == 2) {
                v00 = 0.5f * v00 * (1.f + erff(v00 * 0.70710678118654752f));
                v01 = 0.5f * v01 * (1.f + erff(v01 * 0.70710678118654752f));
                v10 = 0.5f * v10 * (1.f + erff(v10 * 0.70710678118654752f));
                v11 = 0.5f * v11 * (1.f + erff(v11 * 0.70710678118654752f));
            }
            if (RES) {
                v00 += Rp[r0 * N + cn]; v01 += Rp[r0 * N + cn + 1];
                v10 += Rp[r1 * N + cn]; v11 += Rp[r1 * N + cn + 1];
            }
            float2 o0 = {v00, v01}, o1 = {v10, v11};
            *(float2*)&C[r0 * N + cn] = o0;
            *(float2*)&C[r1 * N + cn] = o1;
        }
    }
}

// ---------------------------------------------------------------------------
// Cross scores via TF32 MMA: scores[b,h,v,q] =
//   mask[b,v] ? 0 : (qh_v . kh_q)/sqrt(96) + bias[h]
// A = qh (lda=384), B = kh (A@B^T). 128x128 tile, K=96. grid(4,4,128)
// ---------------------------------------------------------------------------
__global__ __launch_bounds__(128, 2)
void cross_tc(const float* __restrict__ qh, const float* __restrict__ kh,
              const float* __restrict__ att_bias, const int* __restrict__ mask,
              float* __restrict__ scores)
{
    int bh = blockIdx.z;
    int b = bh >> 2, h = bh & 3;
    const float* Ab = qh + (long long)b * 512 * DIM + h * DH;
    const float* Bb = kh + (long long)b * 512 * DIM + h * DH;

    __shared__ float As[128][20];
    __shared__ float Bs[16][136];

    int v0 = blockIdx.y * 128, q0 = blockIdx.x * 128;
    int tid = threadIdx.x;
    int warp = tid >> 5, lane = tid & 31;
    int wm = (warp >> 1) * 64, wn = (warp & 1) * 64;

    float acc[4][8][4];
    #pragma unroll
    for (int i = 0; i < 4; i++)
        #pragma unroll
        for (int j = 0; j < 8; j++)
            #pragma unroll
            for (int r = 0; r < 4; r++) acc[i][j][r] = 0.f;

    const float* Ap = Ab + (long long)(v0 + tid) * DIM;
    const float* Bp = Bb + (long long)(q0 + tid) * DIM;

    float4 av[4], bv[4];
    #pragma unroll
    for (int c = 0; c < 4; c++) {
        av[c] = *(const float4*)(Ap + c * 4);
        bv[c] = *(const float4*)(Bp + c * 4);
    }

    for (int k0 = 0; k0 < DH; k0 += 16) {
        #pragma unroll
        for (int c = 0; c < 4; c++) {
            As[tid][c * 4 + 0] = to_tf32(av[c].x);
            As[tid][c * 4 + 1] = to_tf32(av[c].y);
            As[tid][c * 4 + 2] = to_tf32(av[c].z);
            As[tid][c * 4 + 3] = to_tf32(av[c].w);
            Bs[c * 4 + 0][tid] = to_tf32(bv[c].x);
            Bs[c * 4 + 1][tid] = to_tf32(bv[c].y);
            Bs[c * 4 + 2][tid] = to_tf32(bv[c].z);
            Bs[c * 4 + 3][tid] = to_tf32(bv[c].w);
        }
        __syncthreads();

        if (k0 + 16 < DH) {
            Ap += 16; Bp += 16;
            #pragma unroll
            for (int c = 0; c < 4; c++) {
                av[c] = *(const float4*)(Ap + c * 4);
                bv[c] = *(const float4*)(Bp + c * 4);
            }
        }

        #pragma unroll
        for (int ks = 0; ks < 2; ks++) {
            int ko = ks * 8;
            uint32_t af[4][4], bf[8][2];
            #pragma unroll
            for (int i = 0; i < 4; i++) {
                int mr = wm + i * 16 + (lane >> 2);
                int kc = ko + (lane & 3);
                af[i][0] = __float_as_uint(As[mr][kc]);
                af[i][1] = __float_as_uint(As[mr + 8][kc]);
                af[i][2] = __float_as_uint(As[mr][kc + 4]);
                af[i][3] = __float_as_uint(As[mr + 8][kc + 4]);
            }
            #pragma unroll
            for (int j = 0; j < 8; j++) {
                int nc = wn + j * 8 + (lane >> 2);
                int kr = ko + (lane & 3);
                bf[j][0] = __float_as_uint(Bs[kr][nc]);
                bf[j][1] = __float_as_uint(Bs[kr + 4][nc]);
            }
            #pragma unroll
            for (int i = 0; i < 4; i++)
                #pragma unroll
                for (int j = 0; j < 8; j++)
                    mma_tf32(acc[i][j], af[i], bf[j]);
        }
        __syncthreads();
    }

    const float scale = 0.10206207261596575f; // 1/sqrt(96)
    float biash = att_bias[h];
    float* out = scores + (long long)bh * 512 * 512;
    #pragma unroll
    for (int i = 0; i < 4; i++) {
        int va = v0 + wm + i * 16 + (lane >> 2);
        int vb = va + 8;
        bool ma = (mask[b * 512 + va] != 0);
        bool mb = (mask[b * 512 + vb] != 0);
        #pragma unroll
        for (int j = 0; j < 8; j++) {
            int cq = q0 + wn + j * 8 + (lane & 3) * 2;
            float2 oa, ob;
            oa.x = ma ? 0.f : (acc[i][j][0] * scale + biash);
            oa.y = ma ? 0.f : (acc[i][j][1] * scale + biash);
            ob.x = mb ? 0.f : (acc[i][j][2] * scale + biash);
            ob.y = mb ? 0.f : (acc[i][j][3] * scale + biash);
            *(float2*)&out[(long long)va * 512 + cq] = oa;
            *(float2*)&out[(long long)vb * 512 + cq] = ob;
        }
    }
}

// ---------------------------------------------------------------------------
// Flash self-attention (fp32): out = softmax(QK^T/sqrt(32)) @ V
// ---------------------------------------------------------------------------
__global__ __launch_bounds__(256, 2)
void flash_attn_k(const float* __restrict__ qkv, float* __restrict__ out)
{
    int bh = blockIdx.y;
    int b = bh / TH, h = bh % TH;
    int i0 = blockIdx.x * 64;
    const float* base = qkv + (long long)b * 512 * 288;
    const float* qb = base + h * 32;
    const float* kb = base + 96 + h * 32;
    const float* vb = base + 192 + h * 32;

    __shared__ float qs[64][36];
    __shared__ float ks[64][36];
    __shared__ float vs[64][36];
    __shared__ float ps[64][65];

    int tid = threadIdx.x;
    int r = tid >> 2, tq = tid & 3;

    for (int e = tid; e < 512; e += 256) {
        int row = e >> 3, c4 = (e & 7) * 4;
        *(float4*)&qs[row][c4] = *(const float4*)&qb[(long long)(i0 + row) * 288 + c4];
    }
    __syncthreads();
    float q[32];
    #pragma unroll
    for (int i = 0; i < 8; i++) *(float4*)&q[i * 4] = *(const float4*)&qs[r][i * 4];

    float O[8] = {};
    float mrow = -INFINITY, lrow = 0.f;
    const float scale = 0.1767766952966369f;

    for (int j0 = 0; j0 < 512; j0 += 64) {
        __syncthreads();
        for (int e = tid; e < 512; e += 256) {
            int row = e >> 3, c4 = (e & 7) * 4;
            *(float4*)&ks[row][c4] = *(const float4*)&kb[(long long)(j0 + row) * 288 + c4];
            *(float4*)&vs[row][c4] = *(const float4*)&vb[(long long)(j0 + row) * 288 + c4];
        }
        __syncthreads();

        float s[16];
        #pragma unroll
        for (int jj = 0; jj < 16; jj++) {
            int j = jj * 4 + tq;
            float a = 0.f;
            #pragma unroll
            for (int d4 = 0; d4 < 8; d4++) {
                float4 kk = *(const float4*)&ks[j][d4 * 4];
                a += q[d4*4+0]*kk.x + q[d4*4+1]*kk.y + q[d4*4+2]*kk.z + q[d4*4+3]*kk.w;
            }
            s[jj] = a * scale;
        }
        float smax = s[0];
        #pragma unroll
        for (int jj = 1; jj < 16; jj++) smax = fmaxf(smax, s[jj]);
        #pragma unroll
        for (int o = 1; o < 4; o <<= 1)
            smax = fmaxf(smax, __shfl_xor_sync(0xffffffffu, smax, o));
        float mnew = fmaxf(mrow, smax);
        float corr = __expf(mrow - mnew);
        float psum = 0.f;
        #pragma unroll
        for (int jj = 0; jj < 16; jj++) {
            float p = __expf(s[jj] - mnew);
            ps[r][jj * 4 + tq] = p;
            psum += p;
        }
        #pragma unroll
        for (int o = 1; o < 4; o <<= 1)
            psum += __shfl_xor_sync(0xffffffffu, psum, o);
        lrow = lrow * corr + psum;
        mrow = mnew;
        #pragma unroll
        for (int d = 0; d < 8; d++) O[d] *= corr;
        __syncwarp();

        int d0 = tq * 8;
        #pragma unroll 8
        for (int j = 0; j < 64; j++) {
            float pj = ps[r][j];
            float4 v0 = *(const float4*)&vs[j][d0];
            float4 v1 = *(const float4*)&vs[j][d0 + 4];
            O[0] += pj * v0.x; O[1] += pj * v0.y; O[2] += pj * v0.z; O[3] += pj * v0.w;
            O[4] += pj * v1.x; O[5] += pj * v1.y; O[6] += pj * v1.z; O[7] += pj * v1.w;
        }
    }

    float inv = 1.f / lrow;
    float* ob = out + (long long)(b * 512 + i0 + r) * 96 + h * 32 + tq * 8;
    float4 o0 = {O[0]*inv, O[1]*inv, O[2]*inv, O[3]*inv};
    float4 o1 = {O[4]*inv, O[5]*inv, O[6]*inv, O[7]*inv};
    *(float4*)ob = o0;
    *(float4*)(ob + 4) = o1;
}

// ---------------------------------------------------------------------------
// LayerNorm (rows of 384)
// ---------------------------------------------------------------------------
__global__ void layernorm_k(const float* __restrict__ x, const float* __restrict__ g,
                            const float* __restrict__ b, float* __restrict__ y)
{
    long long row = blockIdx.x;
    const float* xr = x + row * DIM;
    float* yr = y + row * DIM;
    int t = threadIdx.x;

    float v[3], s = 0.f, s2 = 0.f;
    #pragma unroll
    for (int i = 0; i < 3; i++) {
        v[i] = xr[t + 128 * i];
        s += v[i];
        s2 += v[i] * v[i];
    }
    __shared__ float sa[128], sb[128];
    sa[t] = s; sb[t] = s2;
    __syncthreads();
    for (int st = 64; st > 0; st >>= 1) {
        if (t < st) { sa[t] += sa[t + st]; sb[t] += sb[t + st]; }
        __syncthreads();
    }
    float mean = sa[0] * (1.f / DIM);
    float var = sb[0] * (1.f / DIM) - mean * mean;
    float rstd = rsqrtf(var + 1e-5f);
    #pragma unroll
    for (int i = 0; i < 3; i++) {
        int d = t + 128 * i;
        yr[d] = (v[i] - mean) * rstd * g[d] + b[d];
    }
}

// ---------------------------------------------------------------------------
// mask / logits / final head
// ---------------------------------------------------------------------------
__global__ void mask_k(const float* __restrict__ gf, int* __restrict__ mask)
{
    int gw = (blockIdx.x * blockDim.x + threadIdx.x) >> 5;
    int lane = threadIdx.x & 31;
    if (gw >= ROWS) return;
    const float* row = gf + (long long)gw * GD;
    float s = 0.f;
    for (int i = lane; i < GD; i += 32) s += fabsf(row[i]);
    #pragma unroll
    for (int o = 16; o > 0; o >>= 1) s += __shfl_down_sync(0xffffffffu, s, o);
    if (lane == 0) mask[gw] = (s == 0.0f) ? 1 : 0;
}

__global__ void logits_k(const float* __restrict__ ga, const float* __restrict__ u,
                         float* __restrict__ logits)
{
    int bh = blockIdx.x;
    int b = bh >> 2;
    int d = threadIdx.x;
    const float* gp = ga + (long long)b * 512 * DIM + d;
    const float* up = u + (long long)bh * 512 * DIM + d;
    float acc = 0.f;
    for (int v = 0; v < 512; v++) acc += gp[(long long)v * DIM] * up[(long long)v * DIM];
    logits[bh * DIM + d] = acc;
}

__global__ void final_k(const float* __restrict__ logits,
                        const float* __restrict__ bn_g, const float* __restrict__ bn_b,
                        const float* __restrict__ bn_mean, const float* __restrict__ bn_var,
                        const float* __restrict__ Wf, const float* __restrict__ bf,
                        float* __restrict__ out)
{
    int b = blockIdx.x, t = threadIdx.x;
    float pooled = 0.f;
    #pragma unroll
    for (int h = 0; h < 4; h++) {
        const float* lp = logits + (b * 4 + h) * DIM + t * 3;
        pooled += lp[0] + lp[1] + lp[2];
    }
    float bn = (pooled - bn_mean[t]) * rsqrtf(bn_var[t] + 1e-5f) * bn_g[t] + bn_b[t];
    __shared__ float sh[128];
    sh[t] = bn * Wf[t];
    __syncthreads();
    for (int s = 64; s > 0; s >>= 1) {
        if (t < s) sh[t] += sh[t + s];
        __syncthreads();
    }
    if (t == 0) out[b] = sh[0] + bf[0];
}

// ---------------------------------------------------------------------------
// Host side
// ---------------------------------------------------------------------------
struct TrWeights {
    const float *ln1_g, *ln1_b, *Wqkv, *Wo, *bo, *ln2_g, *ln2_b, *W1, *b1, *W2, *b2;
};

static void run_transformer(float* x, float* h, float* qkv, float* attnout,
                            float* ff, const TrWeights& w)
{
    layernorm_k<<<ROWS, 128>>>(x, w.ln1_g, w.ln1_b, h);
    gemm_tc<0, false><<<dim3(3, 128, 1), 128>>>(h, w.Wqkv, nullptr, nullptr, qkv,
                                                ROWS, 288, 384, 0, 0, 0, 1);
    flash_attn_k<<<dim3(8, 96), 256>>>(qkv, attnout);
    gemm_tc<0, true><<<dim3(3, 128, 1), 128>>>(attnout, w.Wo, w.bo, x, x,
                                               ROWS, 384, 96, 0, 0, 0, 1);
    layernorm_k<<<ROWS, 128>>>(x, w.ln2_g, w.ln2_b, h);
    gemm_tc<2, false><<<dim3(1, 128, 1), 128>>>(h, w.W1, w.b1, nullptr, ff,
                                                ROWS, 128, 384, 0, 0, 0, 1);
    gemm_tc<0, true><<<dim3(3, 128, 1), 128>>>(ff, w.W2, w.b2, x, x,
                                               ROWS, 384, 128, 0, 0, 0, 1);
}

extern "C" void kernel_launch(void* const* d_in, const int* in_sizes, int n_in,
                              void* d_out, int out_size)
{
    const float* global_feat = (const float*)d_in[0];
    const float* local_feat  = (const float*)d_in[1];
    const float* Wg   = (const float*)d_in[2];
    const float* bg   = (const float*)d_in[3];
    const float* Wl   = (const float*)d_in[4];
    const float* bl   = (const float*)d_in[5];
    TrWeights tw;
    tw.ln1_g = (const float*)d_in[6];
    tw.ln1_b = (const float*)d_in[7];
    tw.Wqkv  = (const float*)d_in[8];
    tw.Wo    = (const float*)d_in[9];
    tw.bo    = (const float*)d_in[10];
    tw.ln2_g = (const float*)d_in[11];
    tw.ln2_b = (const float*)d_in[12];
    tw.W1    = (const float*)d_in[13];
    tw.b1    = (const float*)d_in[14];
    tw.W2    = (const float*)d_in[15];
    tw.b2    = (const float*)d_in[16];
    const float* Wq       = (const float*)d_in[17];
    const float* Wk       = (const float*)d_in[18];
    const float* att_bias = (const float*)d_in[19];
    const float* bn_g     = (const float*)d_in[20];
    const float* bn_b     = (const float*)d_in[21];
    const float* bn_mean  = (const float*)d_in[22];
    const float* bn_var   = (const float*)d_in[23];
    const float* Wf       = (const float*)d_in[24];
    const float* bf       = (const float*)d_in[25];

    void *p;
    cudaGetSymbolAddress(&p, g_ga);      float* ga      = (float*)p;
    cudaGetSymbolAddress(&p, g_la);      float* la      = (float*)p;
    cudaGetSymbolAddress(&p, g_h);       float* hbuf    = (float*)p;
    cudaGetSymbolAddress(&p, g_qkv);     float* qkv     = (float*)p;
    cudaGetSymbolAddress(&p, g_attnout); float* attnout = (float*)p;
    cudaGetSymbolAddress(&p, g_ff);      float* ff      = (float*)p;
    cudaGetSymbolAddress(&p, g_qh);      float* qh      = (float*)p;
    cudaGetSymbolAddress(&p, g_kh);      float* kh      = (float*)p;
    cudaGetSymbolAddress(&p, g_u);       float* u       = (float*)p;
    cudaGetSymbolAddress(&p, g_logits);  float* logits  = (float*)p;
    cudaGetSymbolAddress(&p, g_mask);    int*   mask    = (int*)p;

    float* out_scalar = (float*)d_out;
    float* scores = out_scalar + BATCH;

    // 1) Input projections (ReLU)
    gemm_tc<1, false><<<dim3(3, 128, 1), 128>>>(global_feat, Wg, bg, nullptr, ga,
                                                ROWS, DIM, GD, 0, 0, 0, 1);
    gemm_tc<1, false><<<dim3(3, 128, 1), 128>>>(local_feat, Wl, bl, nullptr, la,
                                                ROWS, DIM, LD, 0, 0, 0, 1);

    // 2) Shared-weight transformer on both streams
    run_transformer(ga, hbuf, qkv, attnout, ff, tw);
    run_transformer(la, hbuf, qkv, attnout, ff, tw);

    // 3) Cross q/k projections
    gemm_tc<0, false><<<dim3(3, 128, 1), 128>>>(ga, Wq, nullptr, nullptr, qh,
                                                ROWS, DIM, DIM, 0, 0, 0, 1);
    gemm_tc<0, false><<<dim3(3, 128, 1), 128>>>(la, Wk, nullptr, nullptr, kh,
                                                ROWS, DIM, DIM, 0, 0, 0, 1);

    // 4) Mask + cross scores (into d_out)
    mask_k<<<(ROWS * 32 + 255) / 256, 256>>>(global_feat, mask);
    cross_tc<<<dim3(4, 4, 128), 128>>>(qh, kh, att_bias, mask, scores);

    // 5) u[bh] = scores[bh] @ la[b]  (batched, wdiv=4)
    gemm_tc<0, false><<<dim3(3, 4, 128), 128>>>(scores, la, nullptr, nullptr, u,
                                                512, 384, 512,
                                                512LL * 512, 512LL * 384, 512LL * 384, 4);

    // 6) logits + head
    logits_k<<<128, 384>>>(ga, u, logits);
    final_k<<<BATCH, 128>>>(logits, bn_g, bn_b, bn_mean, bn_var, Wf, bf, out_scalar);
}

// round 5
// speedup vs baseline: 2.1809x; 1.0697x over previous
#include <cuda_runtime.h>
#include <math.h>
#include <stdint.h>

// ---------------------------------------------------------------------------
// Problem constants
// ---------------------------------------------------------------------------
#define BATCH 32
#define GD    512
#define LD    256
#define DIM   384
#define TH    3
#define THD   32
#define HOUT  4
#define DH    96
#define HID   128
#define ROWS  (BATCH * 512)   // 16384

// ---------------------------------------------------------------------------
// Scratch
// ---------------------------------------------------------------------------
__device__ float g_ga[ROWS * DIM];
__device__ float g_la[ROWS * DIM];
__device__ float g_h[ROWS * DIM];
__device__ float g_qkv[ROWS * 288];
__device__ float g_attnout[ROWS * 96];
__device__ float g_ff[ROWS * 128];
__device__ float g_qh[ROWS * DIM];
__device__ float g_kh[ROWS * DIM];
__device__ float g_u[128 * 512 * 384];
__device__ float g_logits[128 * 384];
__device__ int   g_mask[ROWS];

// ---------------------------------------------------------------------------
// TF32 helpers
// ---------------------------------------------------------------------------
__device__ __forceinline__ float to_tf32(float x) {
    uint32_t u;
    asm("cvt.rna.tf32.f32 %0, %1;" : "=r"(u) : "f"(x));
    return __uint_as_float(u);
}

__device__ __forceinline__ void mma_tf32(float* d, const uint32_t* a, const uint32_t* b) {
    asm volatile(
        "mma.sync.aligned.m16n8k8.row.col.f32.tf32.tf32.f32 "
        "{%0,%1,%2,%3}, {%4,%5,%6,%7}, {%8,%9}, {%0,%1,%2,%3};"
        : "+f"(d[0]), "+f"(d[1]), "+f"(d[2]), "+f"(d[3])
        : "r"(a[0]), "r"(a[1]), "r"(a[2]), "r"(a[3]), "r"(b[0]), "r"(b[1]));
}

// ---------------------------------------------------------------------------
// TF32 tensor-core GEMM, 256 threads: C = act(A @ W + bias) (+ residual)
// A: [M,K] row-major, W: [K,N] row-major. 128x128 block tile, BK=16.
// 8 warps in 2x4; warp tile 64x32 (4 m-tiles x 4 n-tiles of m16n8k8).
// Batched via blockIdx.z (A += z*sA, C += z*sC, W += (z/wdiv)*sW).
// Requires M%128==0, K%16==0, N%8==0.
// ---------------------------------------------------------------------------
template<int ACT, bool RES>
__global__ __launch_bounds__(256, 2)
void gemm_tc(const float* __restrict__ A, const float* __restrict__ W,
             const float* __restrict__ bias, const float* __restrict__ res,
             float* __restrict__ C, int M, int N, int K,
             long long sA, long long sW, long long sC, int wdiv)
{
    int z = blockIdx.z;
    A += (long long)z * sA;
    C += (long long)z * sC;
    W += (long long)(z / wdiv) * sW;
    const float* Rp = RES ? (res + (long long)z * sC) : nullptr;

    __shared__ float As[128][20];   // [m][k]
    __shared__ float Bs[16][136];   // [k][n]

    int m0 = blockIdx.y * 128, n0 = blockIdx.x * 128;
    int tid = threadIdx.x;
    int warp = tid >> 5, lane = tid & 31;
    int wm = (warp >> 2) * 64;          // 0 or 64
    int wn = (warp & 3) * 32;           // 0,32,64,96

    float acc[4][4][4];
    #pragma unroll
    for (int i = 0; i < 4; i++)
        #pragma unroll
        for (int j = 0; j < 4; j++)
            #pragma unroll
            for (int r = 0; r < 4; r++) acc[i][j][r] = 0.f;

    // A loader: row = tid>>1 (0..127), k-offset = (tid&1)*8
    int arow = tid >> 1, akq = (tid & 1) * 8;
    const float* Ap = A + (long long)(m0 + arow) * K + akq;
    // B loader: k = tid>>4 (0..15), n-offset = (tid&15)*8
    int bkr = tid >> 4, bnq = (tid & 15) * 8;
    const float* Wp = W + (long long)bkr * N + n0 + bnq;
    bool nok = (n0 + bnq < N);   // N%8==0 -> both float4 valid or both out

    float4 av0 = *(const float4*)Ap;
    float4 av1 = *(const float4*)(Ap + 4);
    float4 bv0 = nok ? *(const float4*)Wp       : make_float4(0, 0, 0, 0);
    float4 bv1 = nok ? *(const float4*)(Wp + 4) : make_float4(0, 0, 0, 0);

    for (int k0 = 0; k0 < K; k0 += 16) {
        As[arow][akq + 0] = to_tf32(av0.x);
        As[arow][akq + 1] = to_tf32(av0.y);
        As[arow][akq + 2] = to_tf32(av0.z);
        As[arow][akq + 3] = to_tf32(av0.w);
        As[arow][akq + 4] = to_tf32(av1.x);
        As[arow][akq + 5] = to_tf32(av1.y);
        As[arow][akq + 6] = to_tf32(av1.z);
        As[arow][akq + 7] = to_tf32(av1.w);
        Bs[bkr][bnq + 0] = to_tf32(bv0.x);
        Bs[bkr][bnq + 1] = to_tf32(bv0.y);
        Bs[bkr][bnq + 2] = to_tf32(bv0.z);
        Bs[bkr][bnq + 3] = to_tf32(bv0.w);
        Bs[bkr][bnq + 4] = to_tf32(bv1.x);
        Bs[bkr][bnq + 5] = to_tf32(bv1.y);
        Bs[bkr][bnq + 6] = to_tf32(bv1.z);
        Bs[bkr][bnq + 7] = to_tf32(bv1.w);
        __syncthreads();

        if (k0 + 16 < K) {
            Ap += 16;
            Wp += (long long)16 * N;
            av0 = *(const float4*)Ap;
            av1 = *(const float4*)(Ap + 4);
            if (nok) {
                bv0 = *(const float4*)Wp;
                bv1 = *(const float4*)(Wp + 4);
            }
        }

        #pragma unroll
        for (int ks = 0; ks < 2; ks++) {
            int ko = ks * 8;
            uint32_t af[4][4], bf[4][2];
            #pragma unroll
            for (int i = 0; i < 4; i++) {
                int mr = wm + i * 16 + (lane >> 2);
                int kc = ko + (lane & 3);
                af[i][0] = __float_as_uint(As[mr][kc]);
                af[i][1] = __float_as_uint(As[mr + 8][kc]);
                af[i][2] = __float_as_uint(As[mr][kc + 4]);
                af[i][3] = __float_as_uint(As[mr + 8][kc + 4]);
            }
            #pragma unroll
            for (int j = 0; j < 4; j++) {
                int nc = wn + j * 8 + (lane >> 2);
                int kr = ko + (lane & 3);
                bf[j][0] = __float_as_uint(Bs[kr][nc]);
                bf[j][1] = __float_as_uint(Bs[kr + 4][nc]);
            }
            #pragma unroll
            for (int i = 0; i < 4; i++)
                #pragma unroll
                for (int j = 0; j < 4; j++)
                    mma_tf32(acc[i][j], af[i], bf[j]);
        }
        __syncthreads();
    }

    // Epilogue
    #pragma unroll
    for (int i = 0; i < 4; i++) {
        long long r0 = m0 + wm + i * 16 + (lane >> 2);
        long long r1 = r0 + 8;
        #pragma unroll
        for (int j = 0; j < 4; j++) {
            int cn = n0 + wn + j * 8 + (lane & 3) * 2;
            if (cn >= N) continue;
            float v00 = acc[i][j][0], v01 = acc[i][j][1];
            float v10 = acc[i][j][2], v11 = acc[i][j][3];
            if (bias) {
                float b0 = bias[cn], b1 = bias[cn + 1];
                v00 += b0; v01 += b1; v10 += b0; v11 += b1;
            }
            if (ACT == 1) {
                v00 = fmaxf(v00, 0.f); v01 = fmaxf(v01, 0.f);
                v10 = fmaxf(v10, 0.f); v11 = fmaxf(v11, 0.f);
            }
            if (ACT == 2) {
                v00 = 0.5f * v00 * (1.f + erff(v00 * 0.70710678118654752f));
                v01 = 0.5f * v01 * (1.f + erff(v01 * 0.70710678118654752f));
                v10 = 0.5f * v10 * (1.f + erff(v10 * 0.70710678118654752f));
                v11 = 0.5f * v11 * (1.f + erff(v11 * 0.70710678118654752f));
            }
            if (RES) {
                v00 += Rp[r0 * N + cn]; v01 += Rp[r0 * N + cn + 1];
                v10 += Rp[r1 * N + cn]; v11 += Rp[r1 * N + cn + 1];
            }
            float2 o0 = {v00, v01}, o1 = {v10, v11};
            *(float2*)&C[r0 * N + cn] = o0;
            *(float2*)&C[r1 * N + cn] = o1;
        }
    }
}

// ---------------------------------------------------------------------------
// Cross scores via TF32 MMA (256 threads): scores[b,h,v,q] =
//   mask[b,v] ? 0 : (qh_v . kh_q)/sqrt(96) + bias[h]
// A = qh, B = kh (A@B^T), both lda=384. 128x128 tile, K=96. grid(4,4,128)
// ---------------------------------------------------------------------------
__global__ __launch_bounds__(256, 2)
void cross_tc(const float* __restrict__ qh, const float* __restrict__ kh,
              const float* __restrict__ att_bias, const int* __restrict__ mask,
              float* __restrict__ scores)
{
    int bh = blockIdx.z;
    int b = bh >> 2, h = bh & 3;
    const float* Ab = qh + (long long)b * 512 * DIM + h * DH;
    const float* Bb = kh + (long long)b * 512 * DIM + h * DH;

    __shared__ float As[128][20];
    __shared__ float Bs[16][136];

    int v0 = blockIdx.y * 128, q0 = blockIdx.x * 128;
    int tid = threadIdx.x;
    int warp = tid >> 5, lane = tid & 31;
    int wm = (warp >> 2) * 64;
    int wn = (warp & 3) * 32;

    float acc[4][4][4];
    #pragma unroll
    for (int i = 0; i < 4; i++)
        #pragma unroll
        for (int j = 0; j < 4; j++)
            #pragma unroll
            for (int r = 0; r < 4; r++) acc[i][j][r] = 0.f;

    int arow = tid >> 1, akq = (tid & 1) * 8;
    const float* Ap = Ab + (long long)(v0 + arow) * DIM + akq;
    const float* Bp = Bb + (long long)(q0 + arow) * DIM + akq;

    float4 av0 = *(const float4*)Ap;
    float4 av1 = *(const float4*)(Ap + 4);
    float4 bv0 = *(const float4*)Bp;
    float4 bv1 = *(const float4*)(Bp + 4);

    for (int k0 = 0; k0 < DH; k0 += 16) {
        As[arow][akq + 0] = to_tf32(av0.x);
        As[arow][akq + 1] = to_tf32(av0.y);
        As[arow][akq + 2] = to_tf32(av0.z);
        As[arow][akq + 3] = to_tf32(av0.w);
        As[arow][akq + 4] = to_tf32(av1.x);
        As[arow][akq + 5] = to_tf32(av1.y);
        As[arow][akq + 6] = to_tf32(av1.z);
        As[arow][akq + 7] = to_tf32(av1.w);
        // B transposed into Bs[k][q-row]
        Bs[akq + 0][arow] = to_tf32(bv0.x);
        Bs[akq + 1][arow] = to_tf32(bv0.y);
        Bs[akq + 2][arow] = to_tf32(bv0.z);
        Bs[akq + 3][arow] = to_tf32(bv0.w);
        Bs[akq + 4][arow] = to_tf32(bv1.x);
        Bs[akq + 5][arow] = to_tf32(bv1.y);
        Bs[akq + 6][arow] = to_tf32(bv1.z);
        Bs[akq + 7][arow] = to_tf32(bv1.w);
        __syncthreads();

        if (k0 + 16 < DH) {
            Ap += 16; Bp += 16;
            av0 = *(const float4*)Ap;
            av1 = *(const float4*)(Ap + 4);
            bv0 = *(const float4*)Bp;
            bv1 = *(const float4*)(Bp + 4);
        }

        #pragma unroll
        for (int ks = 0; ks < 2; ks++) {
            int ko = ks * 8;
            uint32_t af[4][4], bf[4][2];
            #pragma unroll
            for (int i = 0; i < 4; i++) {
                int mr = wm + i * 16 + (lane >> 2);
                int kc = ko + (lane & 3);
                af[i][0] = __float_as_uint(As[mr][kc]);
                af[i][1] = __float_as_uint(As[mr + 8][kc]);
                af[i][2] = __float_as_uint(As[mr][kc + 4]);
                af[i][3] = __float_as_uint(As[mr + 8][kc + 4]);
            }
            #pragma unroll
            for (int j = 0; j < 4; j++) {
                int nc = wn + j * 8 + (lane >> 2);
                int kr = ko + (lane & 3);
                bf[j][0] = __float_as_uint(Bs[kr][nc]);
                bf[j][1] = __float_as_uint(Bs[kr + 4][nc]);
            }
            #pragma unroll
            for (int i = 0; i < 4; i++)
                #pragma unroll
                for (int j = 0; j < 4; j++)
                    mma_tf32(acc[i][j], af[i], bf[j]);
        }
        __syncthreads();
    }

    const float scale = 0.10206207261596575f; // 1/sqrt(96)
    float biash = att_bias[h];
    float* out = scores + (long long)bh * 512 * 512;
    #pragma unroll
    for (int i = 0; i < 4; i++) {
        int va = v0 + wm + i * 16 + (lane >> 2);
        int vb = va + 8;
        bool ma = (mask[b * 512 + va] != 0);
        bool mb = (mask[b * 512 + vb] != 0);
        #pragma unroll
        for (int j = 0; j < 4; j++) {
            int cq = q0 + wn + j * 8 + (lane & 3) * 2;
            float2 oa, ob;
            oa.x = ma ? 0.f : (acc[i][j][0] * scale + biash);
            oa.y = ma ? 0.f : (acc[i][j][1] * scale + biash);
            ob.x = mb ? 0.f : (acc[i][j][2] * scale + biash);
            ob.y = mb ? 0.f : (acc[i][j][3] * scale + biash);
            *(float2*)&out[(long long)va * 512 + cq] = oa;
            *(float2*)&out[(long long)vb * 512 + cq] = ob;
        }
    }
}

// ---------------------------------------------------------------------------
// Flash self-attention (fp32): out = softmax(QK^T/sqrt(32)) @ V
// ---------------------------------------------------------------------------
__global__ __launch_bounds__(256, 2)
void flash_attn_k(const float* __restrict__ qkv, float* __restrict__ out)
{
    int bh = blockIdx.y;
    int b = bh / TH, h = bh % TH;
    int i0 = blockIdx.x * 64;
    const float* base = qkv + (long long)b * 512 * 288;
    const float* qb = base + h * 32;
    const float* kb = base + 96 + h * 32;
    const float* vb = base + 192 + h * 32;

    __shared__ float qs[64][36];
    __shared__ float ks[64][36];
    __shared__ float vs[64][36];
    __shared__ float ps[64][65];

    int tid = threadIdx.x;
    int r = tid >> 2, tq = tid & 3;

    for (int e = tid; e < 512; e += 256) {
        int row = e >> 3, c4 = (e & 7) * 4;
        *(float4*)&qs[row][c4] = *(const float4*)&qb[(long long)(i0 + row) * 288 + c4];
    }
    __syncthreads();
    float q[32];
    #pragma unroll
    for (int i = 0; i < 8; i++) *(float4*)&q[i * 4] = *(const float4*)&qs[r][i * 4];

    float O[8] = {};
    float mrow = -INFINITY, lrow = 0.f;
    const float scale = 0.1767766952966369f;

    for (int j0 = 0; j0 < 512; j0 += 64) {
        __syncthreads();
        for (int e = tid; e < 512; e += 256) {
            int row = e >> 3, c4 = (e & 7) * 4;
            *(float4*)&ks[row][c4] = *(const float4*)&kb[(long long)(j0 + row) * 288 + c4];
            *(float4*)&vs[row][c4] = *(const float4*)&vb[(long long)(j0 + row) * 288 + c4];
        }
        __syncthreads();

        float s[16];
        #pragma unroll
        for (int jj = 0; jj < 16; jj++) {
            int j = jj * 4 + tq;
            float a = 0.f;
            #pragma unroll
            for (int d4 = 0; d4 < 8; d4++) {
                float4 kk = *(const float4*)&ks[j][d4 * 4];
                a += q[d4*4+0]*kk.x + q[d4*4+1]*kk.y + q[d4*4+2]*kk.z + q[d4*4+3]*kk.w;
            }
            s[jj] = a * scale;
        }
        float smax = s[0];
        #pragma unroll
        for (int jj = 1; jj < 16; jj++) smax = fmaxf(smax, s[jj]);
        #pragma unroll
        for (int o = 1; o < 4; o <<= 1)
            smax = fmaxf(smax, __shfl_xor_sync(0xffffffffu, smax, o));
        float mnew = fmaxf(mrow, smax);
        float corr = __expf(mrow - mnew);
        float psum = 0.f;
        #pragma unroll
        for (int jj = 0; jj < 16; jj++) {
            float p = __expf(s[jj] - mnew);
            ps[r][jj * 4 + tq] = p;
            psum += p;
        }
        #pragma unroll
        for (int o = 1; o < 4; o <<= 1)
            psum += __shfl_xor_sync(0xffffffffu, psum, o);
        lrow = lrow * corr + psum;
        mrow = mnew;
        #pragma unroll
        for (int d = 0; d < 8; d++) O[d] *= corr;
        __syncwarp();

        int d0 = tq * 8;
        #pragma unroll 8
        for (int j = 0; j < 64; j++) {
            float pj = ps[r][j];
            float4 v0 = *(const float4*)&vs[j][d0];
            float4 v1 = *(const float4*)&vs[j][d0 + 4];
            O[0] += pj * v0.x; O[1] += pj * v0.y; O[2] += pj * v0.z; O[3] += pj * v0.w;
            O[4] += pj * v1.x; O[5] += pj * v1.y; O[6] += pj * v1.z; O[7] += pj * v1.w;
        }
    }

    float inv = 1.f / lrow;
    float* ob = out + (long long)(b * 512 + i0 + r) * 96 + h * 32 + tq * 8;
    float4 o0 = {O[0]*inv, O[1]*inv, O[2]*inv, O[3]*inv};
    float4 o1 = {O[4]*inv, O[5]*inv, O[6]*inv, O[7]*inv};
    *(float4*)ob = o0;
    *(float4*)(ob + 4) = o1;
}

// ---------------------------------------------------------------------------
// LayerNorm (rows of 384)
// ---------------------------------------------------------------------------
__global__ void layernorm_k(const float* __restrict__ x, const float* __restrict__ g,
                            const float* __restrict__ b, float* __restrict__ y)
{
    long long row = blockIdx.x;
    const float* xr = x + row * DIM;
    float* yr = y + row * DIM;
    int t = threadIdx.x;

    float v[3], s = 0.f, s2 = 0.f;
    #pragma unroll
    for (int i = 0; i < 3; i++) {
        v[i] = xr[t + 128 * i];
        s += v[i];
        s2 += v[i] * v[i];
    }
    __shared__ float sa[128], sb[128];
    sa[t] = s; sb[t] = s2;
    __syncthreads();
    for (int st = 64; st > 0; st >>= 1) {
        if (t < st) { sa[t] += sa[t + st]; sb[t] += sb[t + st]; }
        __syncthreads();
    }
    float mean = sa[0] * (1.f / DIM);
    float var = sb[0] * (1.f / DIM) - mean * mean;
    float rstd = rsqrtf(var + 1e-5f);
    #pragma unroll
    for (int i = 0; i < 3; i++) {
        int d = t + 128 * i;
        yr[d] = (v[i] - mean) * rstd * g[d] + b[d];
    }
}

// ---------------------------------------------------------------------------
// mask / logits / final head
// ---------------------------------------------------------------------------
__global__ void mask_k(const float* __restrict__ gf, int* __restrict__ mask)
{
    int gw = (blockIdx.x * blockDim.x + threadIdx.x) >> 5;
    int lane = threadIdx.x & 31;
    if (gw >= ROWS) return;
    const float* row = gf + (long long)gw * GD;
    float s = 0.f;
    for (int i = lane; i < GD; i += 32) s += fabsf(row[i]);
    #pragma unroll
    for (int o = 16; o > 0; o >>= 1) s += __shfl_down_sync(0xffffffffu, s, o);
    if (lane == 0) mask[gw] = (s == 0.0f) ? 1 : 0;
}

__global__ void logits_k(const float* __restrict__ ga, const float* __restrict__ u,
                         float* __restrict__ logits)
{
    int bh = blockIdx.x;
    int b = bh >> 2;
    int d = threadIdx.x;
    const float* gp = ga + (long long)b * 512 * DIM + d;
    const float* up = u + (long long)bh * 512 * DIM + d;
    float acc = 0.f;
    for (int v = 0; v < 512; v++) acc += gp[(long long)v * DIM] * up[(long long)v * DIM];
    logits[bh * DIM + d] = acc;
}

__global__ void final_k(const float* __restrict__ logits,
                        const float* __restrict__ bn_g, const float* __restrict__ bn_b,
                        const float* __restrict__ bn_mean, const float* __restrict__ bn_var,
                        const float* __restrict__ Wf, const float* __restrict__ bf,
                        float* __restrict__ out)
{
    int b = blockIdx.x, t = threadIdx.x;
    float pooled = 0.f;
    #pragma unroll
    for (int h = 0; h < 4; h++) {
        const float* lp = logits + (b * 4 + h) * DIM + t * 3;
        pooled += lp[0] + lp[1] + lp[2];
    }
    float bn = (pooled - bn_mean[t]) * rsqrtf(bn_var[t] + 1e-5f) * bn_g[t] + bn_b[t];
    __shared__ float sh[128];
    sh[t] = bn * Wf[t];
    __syncthreads();
    for (int s = 64; s > 0; s >>= 1) {
        if (t < s) sh[t] += sh[t + s];
        __syncthreads();
    }
    if (t == 0) out[b] = sh[0] + bf[0];
}

// ---------------------------------------------------------------------------
// Host side
// ---------------------------------------------------------------------------
struct TrWeights {
    const float *ln1_g, *ln1_b, *Wqkv, *Wo, *bo, *ln2_g, *ln2_b, *W1, *b1, *W2, *b2;
};

static void run_transformer(float* x, float* h, float* qkv, float* attnout,
                            float* ff, const TrWeights& w)
{
    layernorm_k<<<ROWS, 128>>>(x, w.ln1_g, w.ln1_b, h);
    gemm_tc<0, false><<<dim3(3, 128, 1), 256>>>(h, w.Wqkv, nullptr, nullptr, qkv,
                                                ROWS, 288, 384, 0, 0, 0, 1);
    flash_attn_k<<<dim3(8, 96), 256>>>(qkv, attnout);
    gemm_tc<0, true><<<dim3(3, 128, 1), 256>>>(attnout, w.Wo, w.bo, x, x,
                                               ROWS, 384, 96, 0, 0, 0, 1);
    layernorm_k<<<ROWS, 128>>>(x, w.ln2_g, w.ln2_b, h);
    gemm_tc<2, false><<<dim3(1, 128, 1), 256>>>(h, w.W1, w.b1, nullptr, ff,
                                                ROWS, 128, 384, 0, 0, 0, 1);
    gemm_tc<0, true><<<dim3(3, 128, 1), 256>>>(ff, w.W2, w.b2, x, x,
                                               ROWS, 384, 128, 0, 0, 0, 1);
}

extern "C" void kernel_launch(void* const* d_in, const int* in_sizes, int n_in,
                              void* d_out, int out_size)
{
    const float* global_feat = (const float*)d_in[0];
    const float* local_feat  = (const float*)d_in[1];
    const float* Wg   = (const float*)d_in[2];
    const float* bg   = (const float*)d_in[3];
    const float* Wl   = (const float*)d_in[4];
    const float* bl   = (const float*)d_in[5];
    TrWeights tw;
    tw.ln1_g = (const float*)d_in[6];
    tw.ln1_b = (const float*)d_in[7];
    tw.Wqkv  = (const float*)d_in[8];
    tw.Wo    = (const float*)d_in[9];
    tw.bo    = (const float*)d_in[10];
    tw.ln2_g = (const float*)d_in[11];
    tw.ln2_b = (const float*)d_in[12];
    tw.W1    = (const float*)d_in[13];
    tw.b1    = (const float*)d_in[14];
    tw.W2    = (const float*)d_in[15];
    tw.b2    = (const float*)d_in[16];
    const float* Wq       = (const float*)d_in[17];
    const float* Wk       = (const float*)d_in[18];
    const float* att_bias = (const float*)d_in[19];
    const float* bn_g     = (const float*)d_in[20];
    const float* bn_b     = (const float*)d_in[21];
    const float* bn_mean  = (const float*)d_in[22];
    const float* bn_var   = (const float*)d_in[23];
    const float* Wf       = (const float*)d_in[24];
    const float* bf       = (const float*)d_in[25];

    void *p;
    cudaGetSymbolAddress(&p, g_ga);      float* ga      = (float*)p;
    cudaGetSymbolAddress(&p, g_la);      float* la      = (float*)p;
    cudaGetSymbolAddress(&p, g_h);       float* hbuf    = (float*)p;
    cudaGetSymbolAddress(&p, g_qkv);     float* qkv     = (float*)p;
    cudaGetSymbolAddress(&p, g_attnout); float* attnout = (float*)p;
    cudaGetSymbolAddress(&p, g_ff);      float* ff      = (float*)p;
    cudaGetSymbolAddress(&p, g_qh);      float* qh      = (float*)p;
    cudaGetSymbolAddress(&p, g_kh);      float* kh      = (float*)p;
    cudaGetSymbolAddress(&p, g_u);       float* u       = (float*)p;
    cudaGetSymbolAddress(&p, g_logits);  float* logits  = (float*)p;
    cudaGetSymbolAddress(&p, g_mask);    int*   mask    = (int*)p;

    float* out_scalar = (float*)d_out;
    float* scores = out_scalar + BATCH;

    // 1) Input projections (ReLU)
    gemm_tc<1, false><<<dim3(3, 128, 1), 256>>>(global_feat, Wg, bg, nullptr, ga,
                                                ROWS, DIM, GD, 0, 0, 0, 1);
    gemm_tc<1, false><<<dim3(3, 128, 1), 256>>>(local_feat, Wl, bl, nullptr, la,
                                                ROWS, DIM, LD, 0, 0, 0, 1);

    // 2) Shared-weight transformer on both streams
    run_transformer(ga, hbuf, qkv, attnout, ff, tw);
    run_transformer(la, hbuf, qkv, attnout, ff, tw);

    // 3) Cross q/k projections
    gemm_tc<0, false><<<dim3(3, 128, 1), 256>>>(ga, Wq, nullptr, nullptr, qh,
                                                ROWS, DIM, DIM, 0, 0, 0, 1);
    gemm_tc<0, false><<<dim3(3, 128, 1), 256>>>(la, Wk, nullptr, nullptr, kh,
                                                ROWS, DIM, DIM, 0, 0, 0, 1);

    // 4) Mask + cross scores (into d_out)
    mask_k<<<(ROWS * 32 + 255) / 256, 256>>>(global_feat, mask);
    cross_tc<<<dim3(4, 4, 128), 256>>>(qh, kh, att_bias, mask, scores);

    // 5) u[bh] = scores[bh] @ la[b]  (batched, wdiv=4)
    gemm_tc<0, false><<<dim3(3, 4, 128), 256>>>(scores, la, nullptr, nullptr, u,
                                                512, 384, 512,
                                                512LL * 512, 512LL * 384, 512LL * 384, 4);

    // 6) logits + head
    logits_k<<<128, 384>>>(ga, u, logits);
    final_k<<<BATCH, 128>>>(logits, bn_g, bn_b, bn_mean, bn_var, Wf, bf, out_scalar);
}

// round 7
// speedup vs baseline: 2.3198x; 1.0637x over previous
#include <cuda_runtime.h>
#include <math.h>
#include <stdint.h>

// ---------------------------------------------------------------------------
// Problem constants
// ---------------------------------------------------------------------------
#define BATCH 32
#define GD    512
#define LD    256
#define DIM   384
#define TH    3
#define THD   32
#define HOUT  4
#define DH    96
#define HID   128
#define ROWS  (BATCH * 512)   // 16384

// ---------------------------------------------------------------------------
// Scratch
// ---------------------------------------------------------------------------
__device__ float g_ga[ROWS * DIM];
__device__ float g_la[ROWS * DIM];
__device__ float g_qkv[ROWS * 288];
__device__ float g_attnout[ROWS * 96];
__device__ float g_ff[ROWS * 128];
__device__ float g_qh[ROWS * DIM];
__device__ float g_kh[ROWS * DIM];
__device__ float g_u[128 * 512 * 384];
__device__ float g_logits[128 * 384];
__device__ float g_lnstat[ROWS * 2];
__device__ int   g_mask[ROWS];

// ---------------------------------------------------------------------------
// TF32 helpers
// ---------------------------------------------------------------------------
__device__ __forceinline__ float to_tf32(float x) {
    uint32_t u;
    asm("cvt.rna.tf32.f32 %0, %1;" : "=r"(u) : "f"(x));
    return __uint_as_float(u);
}

__device__ __forceinline__ void mma_tf32(float* d, const uint32_t* a, const uint32_t* b) {
    asm volatile(
        "mma.sync.aligned.m16n8k8.row.col.f32.tf32.tf32.f32 "
        "{%0,%1,%2,%3}, {%4,%5,%6,%7}, {%8,%9}, {%0,%1,%2,%3};"
        : "+f"(d[0]), "+f"(d[1]), "+f"(d[2]), "+f"(d[3])
        : "r"(a[0]), "r"(a[1]), "r"(a[2]), "r"(a[3]), "r"(b[0]), "r"(b[1]));
}

// ---------------------------------------------------------------------------
// Row LN stats: stat[row] = {mean, rstd}. One warp per row.
// ---------------------------------------------------------------------------
__global__ void lnstats_k(const float* __restrict__ x, float* __restrict__ stat)
{
    int row = blockIdx.x * 8 + (threadIdx.x >> 5);
    int lane = threadIdx.x & 31;
    const float* xr = x + (long long)row * DIM;
    float s = 0.f, s2 = 0.f;
    #pragma unroll
    for (int i = 0; i < 12; i++) {
        float v = xr[lane + 32 * i];
        s += v; s2 += v * v;
    }
    #pragma unroll
    for (int o = 16; o > 0; o >>= 1) {
        s  += __shfl_xor_sync(0xffffffffu, s, o);
        s2 += __shfl_xor_sync(0xffffffffu, s2, o);
    }
    if (lane == 0) {
        float mean = s * (1.f / DIM);
        float var = s2 * (1.f / DIM) - mean * mean;
        stat[row * 2] = mean;
        stat[row * 2 + 1] = rsqrtf(var + 1e-5f);
    }
}

// ---------------------------------------------------------------------------
// TF32 tensor-core GEMM, 256 threads, 2-stage double-buffered smem.
// C = act((LNA ? LN(A) : A) @ W + bias) (+ residual)
// A: [M,K] row-major, W: [K,N] row-major. 128x128 block tile, BK=16.
// 8 warps 2x4; warp tile 64x32. Batched via blockIdx.z.
// Requires M%128==0, K%16==0, N%8==0.
// ---------------------------------------------------------------------------
template<int ACT, bool RES, bool LNA>
__global__ __launch_bounds__(256, 2)
void gemm_tc(const float* __restrict__ A, const float* __restrict__ W,
             const float* __restrict__ bias, const float* __restrict__ res,
             float* __restrict__ C,
             const float* __restrict__ lnstat, const float* __restrict__ lng,
             const float* __restrict__ lnb,
             int M, int N, int K,
             long long sA, long long sW, long long sC, int wdiv)
{
    int z = blockIdx.z;
    A += (long long)z * sA;
    C += (long long)z * sC;
    W += (long long)(z / wdiv) * sW;
    const float* Rp = RES ? (res + (long long)z * sC) : nullptr;

    __shared__ float As[2][128][20];
    __shared__ float Bs[2][16][136];

    int m0 = blockIdx.y * 128, n0 = blockIdx.x * 128;
    int tid = threadIdx.x;
    int warp = tid >> 5, lane = tid & 31;
    int wm = (warp >> 2) * 64;
    int wn = (warp & 3) * 32;

    float acc[4][4][4];
    #pragma unroll
    for (int i = 0; i < 4; i++)
        #pragma unroll
        for (int j = 0; j < 4; j++)
            #pragma unroll
            for (int r = 0; r < 4; r++) acc[i][j][r] = 0.f;

    int arow = tid >> 1, akq = (tid & 1) * 8;
    const float* Ap = A + (long long)(m0 + arow) * K + akq;
    int bkr = tid >> 4, bnq = (tid & 15) * 8;
    const float* Wp = W + (long long)bkr * N + n0 + bnq;
    bool nok = (n0 + bnq < N);

    float mean = 0.f, rstd = 0.f;
    if (LNA) {
        mean = lnstat[(m0 + arow) * 2];
        rstd = lnstat[(m0 + arow) * 2 + 1];
    }

    float4 av0 = *(const float4*)Ap;
    float4 av1 = *(const float4*)(Ap + 4);
    float4 bv0 = nok ? *(const float4*)Wp       : make_float4(0, 0, 0, 0);
    float4 bv1 = nok ? *(const float4*)(Wp + 4) : make_float4(0, 0, 0, 0);

    int KT = K >> 4;
    for (int kt = 0; kt < KT; kt++) {
        int buf = kt & 1;
        // Store tile kt (with optional LN transform on A)
        if (LNA) {
            int kg = kt * 16 + akq;
            float4 g0 = *(const float4*)&lng[kg];
            float4 g1 = *(const float4*)&lng[kg + 4];
            float4 b0 = *(const float4*)&lnb[kg];
            float4 b1 = *(const float4*)&lnb[kg + 4];
            As[buf][arow][akq + 0] = to_tf32((av0.x - mean) * rstd * g0.x + b0.x);
            As[buf][arow][akq + 1] = to_tf32((av0.y - mean) * rstd * g0.y + b0.y);
            As[buf][arow][akq + 2] = to_tf32((av0.z - mean) * rstd * g0.z + b0.z);
            As[buf][arow][akq + 3] = to_tf32((av0.w - mean) * rstd * g0.w + b0.w);
            As[buf][arow][akq + 4] = to_tf32((av1.x - mean) * rstd * g1.x + b1.x);
            As[buf][arow][akq + 5] = to_tf32((av1.y - mean) * rstd * g1.y + b1.y);
            As[buf][arow][akq + 6] = to_tf32((av1.z - mean) * rstd * g1.z + b1.z);
            As[buf][arow][akq + 7] = to_tf32((av1.w - mean) * rstd * g1.w + b1.w);
        } else {
            As[buf][arow][akq + 0] = to_tf32(av0.x);
            As[buf][arow][akq + 1] = to_tf32(av0.y);
            As[buf][arow][akq + 2] = to_tf32(av0.z);
            As[buf][arow][akq + 3] = to_tf32(av0.w);
            As[buf][arow][akq + 4] = to_tf32(av1.x);
            As[buf][arow][akq + 5] = to_tf32(av1.y);
            As[buf][arow][akq + 6] = to_tf32(av1.z);
            As[buf][arow][akq + 7] = to_tf32(av1.w);
        }
        Bs[buf][bkr][bnq + 0] = to_tf32(bv0.x);
        Bs[buf][bkr][bnq + 1] = to_tf32(bv0.y);
        Bs[buf][bkr][bnq + 2] = to_tf32(bv0.z);
        Bs[buf][bkr][bnq + 3] = to_tf32(bv0.w);
        Bs[buf][bkr][bnq + 4] = to_tf32(bv1.x);
        Bs[buf][bkr][bnq + 5] = to_tf32(bv1.y);
        Bs[buf][bkr][bnq + 6] = to_tf32(bv1.z);
        Bs[buf][bkr][bnq + 7] = to_tf32(bv1.w);

        // Prefetch next tile into registers (overlaps with compute below)
        if (kt + 1 < KT) {
            Ap += 16;
            Wp += (long long)16 * N;
            av0 = *(const float4*)Ap;
            av1 = *(const float4*)(Ap + 4);
            if (nok) {
                bv0 = *(const float4*)Wp;
                bv1 = *(const float4*)(Wp + 4);
            }
        }

        __syncthreads();   // tile kt visible; prior compute on this buffer done

        #pragma unroll
        for (int ks = 0; ks < 2; ks++) {
            int ko = ks * 8;
            uint32_t af[4][4], bf[4][2];
            #pragma unroll
            for (int i = 0; i < 4; i++) {
                int mr = wm + i * 16 + (lane >> 2);
                int kc = ko + (lane & 3);
                af[i][0] = __float_as_uint(As[buf][mr][kc]);
                af[i][1] = __float_as_uint(As[buf][mr + 8][kc]);
                af[i][2] = __float_as_uint(As[buf][mr][kc + 4]);
                af[i][3] = __float_as_uint(As[buf][mr + 8][kc + 4]);
            }
            #pragma unroll
            for (int j = 0; j < 4; j++) {
                int nc = wn + j * 8 + (lane >> 2);
                int kr = ko + (lane & 3);
                bf[j][0] = __float_as_uint(Bs[buf][kr][nc]);
                bf[j][1] = __float_as_uint(Bs[buf][kr + 4][nc]);
            }
            #pragma unroll
            for (int i = 0; i < 4; i++)
                #pragma unroll
                for (int j = 0; j < 4; j++)
                    mma_tf32(acc[i][j], af[i], bf[j]);
        }
        // no second barrier: next iteration writes the OTHER buffer
    }

    // Epilogue
    #pragma unroll
    for (int i = 0; i < 4; i++) {
        long long r0 = m0 + wm + i * 16 + (lane >> 2);
        long long r1 = r0 + 8;
        #pragma unroll
        for (int j = 0; j < 4; j++) {
            int cn = n0 + wn + j * 8 + (lane & 3) * 2;
            if (cn >= N) continue;
            float v00 = acc[i][j][0], v01 = acc[i][j][1];
            float v10 = acc[i][j][2], v11 = acc[i][j][3];
            if (bias) {
                float b0 = bias[cn], b1 = bias[cn + 1];
                v00 += b0; v01 += b1; v10 += b0; v11 += b1;
            }
            if (ACT == 1) {
                v00 = fmaxf(v00, 0.f); v01 = fmaxf(v01, 0.f);
                v10 = fmaxf(v10, 0.f); v11 = fmaxf(v11, 0.f);
            }
            if (ACT == 2) {
                v00 = 0.5f * v00 * (1.f + erff(v00 * 0.70710678118654752f));
                v01 = 0.5f * v01 * (1.f + erff(v01 * 0.70710678118654752f));
                v10 = 0.5f * v10 * (1.f + erff(v10 * 0.70710678118654752f));
                v11 = 0.5f * v11 * (1.f + erff(v11 * 0.70710678118654752f));
            }
            if (RES) {
                v00 += Rp[r0 * N + cn]; v01 += Rp[r0 * N + cn + 1];
                v10 += Rp[r1 * N + cn]; v11 += Rp[r1 * N + cn + 1];
            }
            float2 o0 = {v00, v01}, o1 = {v10, v11};
            *(float2*)&C[r0 * N + cn] = o0;
            *(float2*)&C[r1 * N + cn] = o1;
        }
    }
}

// ---------------------------------------------------------------------------
// Cross scores via TF32 MMA, double-buffered: scores[b,h,v,q] =
//   mask[b,v] ? 0 : (qh_v . kh_q)/sqrt(96) + bias[h]
// ---------------------------------------------------------------------------
__global__ __launch_bounds__(256, 2)
void cross_tc(const float* __restrict__ qh, const float* __restrict__ kh,
              const float* __restrict__ att_bias, const int* __restrict__ mask,
              float* __restrict__ scores)
{
    int bh = blockIdx.z;
    int b = bh >> 2, h = bh & 3;
    const float* Ab = qh + (long long)b * 512 * DIM + h * DH;
    const float* Bb = kh + (long long)b * 512 * DIM + h * DH;

    __shared__ float As[2][128][20];
    __shared__ float Bs[2][16][136];

    int v0 = blockIdx.y * 128, q0 = blockIdx.x * 128;
    int tid = threadIdx.x;
    int warp = tid >> 5, lane = tid & 31;
    int wm = (warp >> 2) * 64;
    int wn = (warp & 3) * 32;

    float acc[4][4][4];
    #pragma unroll
    for (int i = 0; i < 4; i++)
        #pragma unroll
        for (int j = 0; j < 4; j++)
            #pragma unroll
            for (int r = 0; r < 4; r++) acc[i][j][r] = 0.f;

    int arow = tid >> 1, akq = (tid & 1) * 8;
    const float* Ap = Ab + (long long)(v0 + arow) * DIM + akq;
    const float* Bp = Bb + (long long)(q0 + arow) * DIM + akq;

    float4 av0 = *(const float4*)Ap;
    float4 av1 = *(const float4*)(Ap + 4);
    float4 bv0 = *(const float4*)Bp;
    float4 bv1 = *(const float4*)(Bp + 4);

    const int KT = DH / 16;   // 6
    for (int kt = 0; kt < KT; kt++) {
        int buf = kt & 1;
        As[buf][arow][akq + 0] = to_tf32(av0.x);
        As[buf][arow][akq + 1] = to_tf32(av0.y);
        As[buf][arow][akq + 2] = to_tf32(av0.z);
        As[buf][arow][akq + 3] = to_tf32(av0.w);
        As[buf][arow][akq + 4] = to_tf32(av1.x);
        As[buf][arow][akq + 5] = to_tf32(av1.y);
        As[buf][arow][akq + 6] = to_tf32(av1.z);
        As[buf][arow][akq + 7] = to_tf32(av1.w);
        Bs[buf][akq + 0][arow] = to_tf32(bv0.x);
        Bs[buf][akq + 1][arow] = to_tf32(bv0.y);
        Bs[buf][akq + 2][arow] = to_tf32(bv0.z);
        Bs[buf][akq + 3][arow] = to_tf32(bv0.w);
        Bs[buf][akq + 4][arow] = to_tf32(bv1.x);
        Bs[buf][akq + 5][arow] = to_tf32(bv1.y);
        Bs[buf][akq + 6][arow] = to_tf32(bv1.z);
        Bs[buf][akq + 7][arow] = to_tf32(bv1.w);

        if (kt + 1 < KT) {
            Ap += 16; Bp += 16;
            av0 = *(const float4*)Ap;
            av1 = *(const float4*)(Ap + 4);
            bv0 = *(const float4*)Bp;
            bv1 = *(const float4*)(Bp + 4);
        }
        __syncthreads();

        #pragma unroll
        for (int ks = 0; ks < 2; ks++) {
            int ko = ks * 8;
            uint32_t af[4][4], bf[4][2];
            #pragma unroll
            for (int i = 0; i < 4; i++) {
                int mr = wm + i * 16 + (lane >> 2);
                int kc = ko + (lane & 3);
                af[i][0] = __float_as_uint(As[buf][mr][kc]);
                af[i][1] = __float_as_uint(As[buf][mr + 8][kc]);
                af[i][2] = __float_as_uint(As[buf][mr][kc + 4]);
                af[i][3] = __float_as_uint(As[buf][mr + 8][kc + 4]);
            }
            #pragma unroll
            for (int j = 0; j < 4; j++) {
                int nc = wn + j * 8 + (lane >> 2);
                int kr = ko + (lane & 3);
                bf[j][0] = __float_as_uint(Bs[buf][kr][nc]);
                bf[j][1] = __float_as_uint(Bs[buf][kr + 4][nc]);
            }
            #pragma unroll
            for (int i = 0; i < 4; i++)
                #pragma unroll
                for (int j = 0; j < 4; j++)
                    mma_tf32(acc[i][j], af[i], bf[j]);
        }
    }

    const float scale = 0.10206207261596575f; // 1/sqrt(96)
    float biash = att_bias[h];
    float* out = scores + (long long)bh * 512 * 512;
    #pragma unroll
    for (int i = 0; i < 4; i++) {
        int va = v0 + wm + i * 16 + (lane >> 2);
        int vb = va + 8;
        bool ma = (mask[b * 512 + va] != 0);
        bool mb = (mask[b * 512 + vb] != 0);
        #pragma unroll
        for (int j = 0; j < 4; j++) {
            int cq = q0 + wn + j * 8 + (lane & 3) * 2;
            float2 oa, ob;
            oa.x = ma ? 0.f : (acc[i][j][0] * scale + biash);
            oa.y = ma ? 0.f : (acc[i][j][1] * scale + biash);
            ob.x = mb ? 0.f : (acc[i][j][2] * scale + biash);
            ob.y = mb ? 0.f : (acc[i][j][3] * scale + biash);
            *(float2*)&out[(long long)va * 512 + cq] = oa;
            *(float2*)&out[(long long)vb * 512 + cq] = ob;
        }
    }
}

// ---------------------------------------------------------------------------
// Flash self-attention (fp32): out = softmax(QK^T/sqrt(32)) @ V
// ---------------------------------------------------------------------------
__global__ __launch_bounds__(256, 2)
void flash_attn_k(const float* __restrict__ qkv, float* __restrict__ out)
{
    int bh = blockIdx.y;
    int b = bh / TH, h = bh % TH;
    int i0 = blockIdx.x * 64;
    const float* base = qkv + (long long)b * 512 * 288;
    const float* qb = base + h * 32;
    const float* kb = base + 96 + h * 32;
    const float* vb = base + 192 + h * 32;

    __shared__ float qs[64][36];
    __shared__ float ks[64][36];
    __shared__ float vs[64][36];
    __shared__ float ps[64][65];

    int tid = threadIdx.x;
    int r = tid >> 2, tq = tid & 3;

    for (int e = tid; e < 512; e += 256) {
        int row = e >> 3, c4 = (e & 7) * 4;
        *(float4*)&qs[row][c4] = *(const float4*)&qb[(long long)(i0 + row) * 288 + c4];
    }
    __syncthreads();
    float q[32];
    #pragma unroll
    for (int i = 0; i < 8; i++) *(float4*)&q[i * 4] = *(const float4*)&qs[r][i * 4];

    float O[8] = {};
    float mrow = -INFINITY, lrow = 0.f;
    const float scale = 0.1767766952966369f;

    for (int j0 = 0; j0 < 512; j0 += 64) {
        __syncthreads();
        for (int e = tid; e < 512; e += 256) {
            int row = e >> 3, c4 = (e & 7) * 4;
            *(float4*)&ks[row][c4] = *(const float4*)&kb[(long long)(j0 + row) * 288 + c4];
            *(float4*)&vs[row][c4] = *(const float4*)&vb[(long long)(j0 + row) * 288 + c4];
        }
        __syncthreads();

        float s[16];
        #pragma unroll
        for (int jj = 0; jj < 16; jj++) {
            int j = jj * 4 + tq;
            float a = 0.f;
            #pragma unroll
            for (int d4 = 0; d4 < 8; d4++) {
                float4 kk = *(const float4*)&ks[j][d4 * 4];
                a += q[d4*4+0]*kk.x + q[d4*4+1]*kk.y + q[d4*4+2]*kk.z + q[d4*4+3]*kk.w;
            }
            s[jj] = a * scale;
        }
        float smax = s[0];
        #pragma unroll
        for (int jj = 1; jj < 16; jj++) smax = fmaxf(smax, s[jj]);
        #pragma unroll
        for (int o = 1; o < 4; o <<= 1)
            smax = fmaxf(smax, __shfl_xor_sync(0xffffffffu, smax, o));
        float mnew = fmaxf(mrow, smax);
        float corr = __expf(mrow - mnew);
        float psum = 0.f;
        #pragma unroll
        for (int jj = 0; jj < 16; jj++) {
            float p = __expf(s[jj] - mnew);
            ps[r][jj * 4 + tq] = p;
            psum += p;
        }
        #pragma unroll
        for (int o = 1; o < 4; o <<= 1)
            psum += __shfl_xor_sync(0xffffffffu, psum, o);
        lrow = lrow * corr + psum;
        mrow = mnew;
        #pragma unroll
        for (int d = 0; d < 8; d++) O[d] *= corr;
        __syncwarp();

        int d0 = tq * 8;
        #pragma unroll 8
        for (int j = 0; j < 64; j++) {
            float pj = ps[r][j];
            float4 v0 = *(const float4*)&vs[j][d0];
            float4 v1 = *(const float4*)&vs[j][d0 + 4];
            O[0] += pj * v0.x; O[1] += pj * v0.y; O[2] += pj * v0.z; O[3] += pj * v0.w;
            O[4] += pj * v1.x; O[5] += pj * v1.y; O[6] += pj * v1.z; O[7] += pj * v1.w;
        }
    }

    float inv = 1.f / lrow;
    float* ob = out + (long long)(b * 512 + i0 + r) * 96 + h * 32 + tq * 8;
    float4 o0 = {O[0]*inv, O[1]*inv, O[2]*inv, O[3]*inv};
    float4 o1 = {O[4]*inv, O[5]*inv, O[6]*inv, O[7]*inv};
    *(float4*)ob = o0;
    *(float4*)(ob + 4) = o1;
}

// ---------------------------------------------------------------------------
// mask / logits / final head
// ---------------------------------------------------------------------------
__global__ void mask_k(const float* __restrict__ gf, int* __restrict__ mask)
{
    int gw = (blockIdx.x * blockDim.x + threadIdx.x) >> 5;
    int lane = threadIdx.x & 31;
    if (gw >= ROWS) return;
    const float* row = gf + (long long)gw * GD;
    float s = 0.f;
    for (int i = lane; i < GD; i += 32) s += fabsf(row[i]);
    #pragma unroll
    for (int o = 16; o > 0; o >>= 1) s += __shfl_down_sync(0xffffffffu, s, o);
    if (lane == 0) mask[gw] = (s == 0.0f) ? 1 : 0;
}

__global__ void logits_k(const float* __restrict__ ga, const float* __restrict__ u,
                         float* __restrict__ logits)
{
    int bh = blockIdx.x;
    int b = bh >> 2;
    int d = threadIdx.x;
    const float* gp = ga + (long long)b * 512 * DIM + d;
    const float* up = u + (long long)bh * 512 * DIM + d;
    float acc = 0.f;
    for (int v = 0; v < 512; v++) acc += gp[(long long)v * DIM] * up[(long long)v * DIM];
    logits[bh * DIM + d] = acc;
}

__global__ void final_k(const float* __restrict__ logits,
                        const float* __restrict__ bn_g, const float* __restrict__ bn_b,
                        const float* __restrict__ bn_mean, const float* __restrict__ bn_var,
                        const float* __restrict__ Wf, const float* __restrict__ bf,
                        float* __restrict__ out)
{
    int b = blockIdx.x, t = threadIdx.x;
    float pooled = 0.f;
    #pragma unroll
    for (int h = 0; h < 4; h++) {
        const float* lp = logits + (b * 4 + h) * DIM + t * 3;
        pooled += lp[0] + lp[1] + lp[2];
    }
    float bn = (pooled - bn_mean[t]) * rsqrtf(bn_var[t] + 1e-5f) * bn_g[t] + bn_b[t];
    __shared__ float sh[128];
    sh[t] = bn * Wf[t];
    __syncthreads();
    for (int s = 64; s > 0; s >>= 1) {
        if (t < s) sh[t] += sh[t + s];
        __syncthreads();
    }
    if (t == 0) out[b] = sh[0] + bf[0];
}

// ---------------------------------------------------------------------------
// Host side
// ---------------------------------------------------------------------------
struct TrWeights {
    const float *ln1_g, *ln1_b, *Wqkv, *Wo, *bo, *ln2_g, *ln2_b, *W1, *b1, *W2, *b2;
};

static void run_transformer(float* x, float* lnstat, float* qkv, float* attnout,
                            float* ff, const TrWeights& w)
{
    lnstats_k<<<ROWS / 8, 256>>>(x, lnstat);
    gemm_tc<0, false, true><<<dim3(3, 128, 1), 256>>>(x, w.Wqkv, nullptr, nullptr, qkv,
                                                      lnstat, w.ln1_g, w.ln1_b,
                                                      ROWS, 288, 384, 0, 0, 0, 1);
    flash_attn_k<<<dim3(8, 96), 256>>>(qkv, attnout);
    gemm_tc<0, true, false><<<dim3(3, 128, 1), 256>>>(attnout, w.Wo, w.bo, x, x,
                                                      nullptr, nullptr, nullptr,
                                                      ROWS, 384, 96, 0, 0, 0, 1);
    lnstats_k<<<ROWS / 8, 256>>>(x, lnstat);
    gemm_tc<2, false, true><<<dim3(1, 128, 1), 256>>>(x, w.W1, w.b1, nullptr, ff,
                                                      lnstat, w.ln2_g, w.ln2_b,
                                                      ROWS, 128, 384, 0, 0, 0, 1);
    gemm_tc<0, true, false><<<dim3(3, 128, 1), 256>>>(ff, w.W2, w.b2, x, x,
                                                      nullptr, nullptr, nullptr,
                                                      ROWS, 384, 128, 0, 0, 0, 1);
}

extern "C" void kernel_launch(void* const* d_in, const int* in_sizes, int n_in,
                              void* d_out, int out_size)
{
    const float* global_feat = (const float*)d_in[0];
    const float* local_feat  = (const float*)d_in[1];
    const float* Wg   = (const float*)d_in[2];
    const float* bg   = (const float*)d_in[3];
    const float* Wl   = (const float*)d_in[4];
    const float* bl   = (const float*)d_in[5];
    TrWeights tw;
    tw.ln1_g = (const float*)d_in[6];
    tw.ln1_b = (const float*)d_in[7];
    tw.Wqkv  = (const float*)d_in[8];
    tw.Wo    = (const float*)d_in[9];
    tw.bo    = (const float*)d_in[10];
    tw.ln2_g = (const float*)d_in[11];
    tw.ln2_b = (const float*)d_in[12];
    tw.W1    = (const float*)d_in[13];
    tw.b1    = (const float*)d_in[14];
    tw.W2    = (const float*)d_in[15];
    tw.b2    = (const float*)d_in[16];
    const float* Wq       = (const float*)d_in[17];
    const float* Wk       = (const float*)d_in[18];
    const float* att_bias = (const float*)d_in[19];
    const float* bn_g     = (const float*)d_in[20];
    const float* bn_b     = (const float*)d_in[21];
    const float* bn_mean  = (const float*)d_in[22];
    const float* bn_var   = (const float*)d_in[23];
    const float* Wf       = (const float*)d_in[24];
    const float* bf       = (const float*)d_in[25];

    void *p;
    cudaGetSymbolAddress(&p, g_ga);      float* ga      = (float*)p;
    cudaGetSymbolAddress(&p, g_la);      float* la      = (float*)p;
    cudaGetSymbolAddress(&p, g_qkv);     float* qkv     = (float*)p;
    cudaGetSymbolAddress(&p, g_attnout); float* attnout = (float*)p;
    cudaGetSymbolAddress(&p, g_ff);      float* ff      = (float*)p;
    cudaGetSymbolAddress(&p, g_qh);      float* qh      = (float*)p;
    cudaGetSymbolAddress(&p, g_kh);      float* kh      = (float*)p;
    cudaGetSymbolAddress(&p, g_u);       float* u       = (float*)p;
    cudaGetSymbolAddress(&p, g_logits);  float* logits  = (float*)p;
    cudaGetSymbolAddress(&p, g_lnstat);  float* lnstat  = (float*)p;
    cudaGetSymbolAddress(&p, g_mask);    int*   mask    = (int*)p;

    float* out_scalar = (float*)d_out;
    float* scores = out_scalar + BATCH;

    // 1) Input projections (ReLU)
    gemm_tc<1, false, false><<<dim3(3, 128, 1), 256>>>(global_feat, Wg, bg, nullptr, ga,
                                                       nullptr, nullptr, nullptr,
                                                       ROWS, DIM, GD, 0, 0, 0, 1);
    gemm_tc<1, false, false><<<dim3(3, 128, 1), 256>>>(local_feat, Wl, bl, nullptr, la,
                                                       nullptr, nullptr, nullptr,
                                                       ROWS, DIM, LD, 0, 0, 0, 1);

    // 2) Shared-weight transformer on both streams
    run_transformer(ga, lnstat, qkv, attnout, ff, tw);
    run_transformer(la, lnstat, qkv, attnout, ff, tw);

    // 3) Cross q/k projections
    gemm_tc<0, false, false><<<dim3(3, 128, 1), 256>>>(ga, Wq, nullptr, nullptr, qh,
                                                       nullptr, nullptr, nullptr,
                                                       ROWS, DIM, DIM, 0, 0, 0, 1);
    gemm_tc<0, false, false><<<dim3(3, 128, 1), 256>>>(la, Wk, nullptr, nullptr, kh,
                                                       nullptr, nullptr, nullptr,
                                                       ROWS, DIM, DIM, 0, 0, 0, 1);

    // 4) Mask + cross scores (into d_out)
    mask_k<<<(ROWS * 32 + 255) / 256, 256>>>(global_feat, mask);
    cross_tc<<<dim3(4, 4, 128), 256>>>(qh, kh, att_bias, mask, scores);

    // 5) u[bh] = scores[bh] @ la[b]  (batched, wdiv=4)
    gemm_tc<0, false, false><<<dim3(3, 4, 128), 256>>>(scores, la, nullptr, nullptr, u,
                                                       nullptr, nullptr, nullptr,
                                                       512, 384, 512,
                                                       512LL * 512, 512LL * 384, 512LL * 384, 4);

    // 6) logits + head
    logits_k<<<128, 384>>>(ga, u, logits);
    final_k<<<BATCH, 128>>>(logits, bn_g, bn_b, bn_mean, bn_var, Wf, bf, out_scalar);
}

// round 8
// speedup vs baseline: 2.3996x; 1.0344x over previous
#include <cuda_runtime.h>
#include <math.h>
#include <stdint.h>

// ---------------------------------------------------------------------------
// Problem constants
// ---------------------------------------------------------------------------
#define BATCH 32
#define GD    512
#define LD    256
#define DIM   384
#define TH    3
#define THD   32
#define HOUT  4
#define DH    96
#define HID   128
#define ROWS  (BATCH * 512)   // 16384

// ---------------------------------------------------------------------------
// Scratch
// ---------------------------------------------------------------------------
__device__ float g_ga[ROWS * DIM];
__device__ float g_la[ROWS * DIM];
__device__ float g_qkv[ROWS * 288];
__device__ float g_attnout[ROWS * 96];
__device__ float g_ff[ROWS * 128];
__device__ float g_qh[ROWS * DIM];
__device__ float g_kh[ROWS * DIM];
__device__ float g_lpart[128 * 4 * 384];   // logits partials [bh][vblk][d]
__device__ float g_lnstat[ROWS * 2];
__device__ int   g_mask[ROWS];

// ---------------------------------------------------------------------------
// TF32 / ldmatrix helpers
// ---------------------------------------------------------------------------
__device__ __forceinline__ float to_tf32(float x) {
    uint32_t u;
    asm("cvt.rna.tf32.f32 %0, %1;" : "=r"(u) : "f"(x));
    return __uint_as_float(u);
}

__device__ __forceinline__ void mma_tf32(float* d, const uint32_t* a, const uint32_t* b) {
    asm volatile(
        "mma.sync.aligned.m16n8k8.row.col.f32.tf32.tf32.f32 "
        "{%0,%1,%2,%3}, {%4,%5,%6,%7}, {%8,%9}, {%0,%1,%2,%3};"
        : "+f"(d[0]), "+f"(d[1]), "+f"(d[2]), "+f"(d[3])
        : "r"(a[0]), "r"(a[1]), "r"(a[2]), "r"(a[3]), "r"(b[0]), "r"(b[1]));
}

__device__ __forceinline__ uint32_t smem_u32(const void* p) {
    return (uint32_t)__cvta_generic_to_shared(p);
}

// Loads the 4 tf32 A-fragments of one m16 x k8 tile (8x8-b32 quads) in one inst.
__device__ __forceinline__ void ldsm_x4(uint32_t* r, uint32_t addr) {
    asm volatile("ldmatrix.sync.aligned.m8n8.x4.shared.b16 {%0,%1,%2,%3}, [%4];"
        : "=r"(r[0]), "=r"(r[1]), "=r"(r[2]), "=r"(r[3]) : "r"(addr));
}

// ---------------------------------------------------------------------------
// Row LN stats: stat[row] = {mean, rstd}. One warp per row.
// ---------------------------------------------------------------------------
__global__ void lnstats_k(const float* __restrict__ x, float* __restrict__ stat)
{
    int row = blockIdx.x * 8 + (threadIdx.x >> 5);
    int lane = threadIdx.x & 31;
    const float* xr = x + (long long)row * DIM;
    float s = 0.f, s2 = 0.f;
    #pragma unroll
    for (int i = 0; i < 12; i++) {
        float v = xr[lane + 32 * i];
        s += v; s2 += v * v;
    }
    #pragma unroll
    for (int o = 16; o > 0; o >>= 1) {
        s  += __shfl_xor_sync(0xffffffffu, s, o);
        s2 += __shfl_xor_sync(0xffffffffu, s2, o);
    }
    if (lane == 0) {
        float mean = s * (1.f / DIM);
        float var = s2 * (1.f / DIM) - mean * mean;
        stat[row * 2] = mean;
        stat[row * 2 + 1] = rsqrtf(var + 1e-5f);
    }
}

// ---------------------------------------------------------------------------
// TF32 GEMM, 256 thr, double-buffered, ldmatrix A-frags.
// C = act((LNA ? LN(A) : A) @ W + bias) (+ residual)
// ---------------------------------------------------------------------------
template<int ACT, bool RES, bool LNA>
__global__ __launch_bounds__(256, 2)
void gemm_tc(const float* __restrict__ A, const float* __restrict__ W,
             const float* __restrict__ bias, const float* __restrict__ res,
             float* __restrict__ C,
             const float* __restrict__ lnstat, const float* __restrict__ lng,
             const float* __restrict__ lnb,
             int M, int N, int K,
             long long sA, long long sW, long long sC, int wdiv)
{
    int z = blockIdx.z;
    A += (long long)z * sA;
    C += (long long)z * sC;
    W += (long long)(z / wdiv) * sW;
    const float* Rp = RES ? (res + (long long)z * sC) : nullptr;

    __shared__ __align__(16) float As[2][128][20];
    __shared__ __align__(16) float Bs[2][16][136];

    int m0 = blockIdx.y * 128, n0 = blockIdx.x * 128;
    int tid = threadIdx.x;
    int warp = tid >> 5, lane = tid & 31;
    int wm = (warp >> 2) * 64;
    int wn = (warp & 3) * 32;

    float acc[4][4][4];
    #pragma unroll
    for (int i = 0; i < 4; i++)
        #pragma unroll
        for (int j = 0; j < 4; j++)
            #pragma unroll
            for (int r = 0; r < 4; r++) acc[i][j][r] = 0.f;

    int arow = tid >> 1, akq = (tid & 1) * 8;
    const float* Ap = A + (long long)(m0 + arow) * K + akq;
    int bkr = tid >> 4, bnq = (tid & 15) * 8;
    const float* Wp = W + (long long)bkr * N + n0 + bnq;
    bool nok = (n0 + bnq < N);

    float mean = 0.f, rstd = 0.f;
    if (LNA) {
        mean = lnstat[(m0 + arow) * 2];
        rstd = lnstat[(m0 + arow) * 2 + 1];
    }

    // ldmatrix per-thread source row/col within tile
    int lrow = wm + (lane & 15);
    int lcol = (lane >> 4) * 4;

    float4 av0 = *(const float4*)Ap;
    float4 av1 = *(const float4*)(Ap + 4);
    float4 bv0 = nok ? *(const float4*)Wp       : make_float4(0, 0, 0, 0);
    float4 bv1 = nok ? *(const float4*)(Wp + 4) : make_float4(0, 0, 0, 0);

    int KT = K >> 4;
    for (int kt = 0; kt < KT; kt++) {
        int buf = kt & 1;
        if (LNA) {
            int kg = kt * 16 + akq;
            float4 g0 = *(const float4*)&lng[kg];
            float4 g1 = *(const float4*)&lng[kg + 4];
            float4 b0 = *(const float4*)&lnb[kg];
            float4 b1 = *(const float4*)&lnb[kg + 4];
            As[buf][arow][akq + 0] = to_tf32((av0.x - mean) * rstd * g0.x + b0.x);
            As[buf][arow][akq + 1] = to_tf32((av0.y - mean) * rstd * g0.y + b0.y);
            As[buf][arow][akq + 2] = to_tf32((av0.z - mean) * rstd * g0.z + b0.z);
            As[buf][arow][akq + 3] = to_tf32((av0.w - mean) * rstd * g0.w + b0.w);
            As[buf][arow][akq + 4] = to_tf32((av1.x - mean) * rstd * g1.x + b1.x);
            As[buf][arow][akq + 5] = to_tf32((av1.y - mean) * rstd * g1.y + b1.y);
            As[buf][arow][akq + 6] = to_tf32((av1.z - mean) * rstd * g1.z + b1.z);
            As[buf][arow][akq + 7] = to_tf32((av1.w - mean) * rstd * g1.w + b1.w);
        } else {
            As[buf][arow][akq + 0] = to_tf32(av0.x);
            As[buf][arow][akq + 1] = to_tf32(av0.y);
            As[buf][arow][akq + 2] = to_tf32(av0.z);
            As[buf][arow][akq + 3] = to_tf32(av0.w);
            As[buf][arow][akq + 4] = to_tf32(av1.x);
            As[buf][arow][akq + 5] = to_tf32(av1.y);
            As[buf][arow][akq + 6] = to_tf32(av1.z);
            As[buf][arow][akq + 7] = to_tf32(av1.w);
        }
        Bs[buf][bkr][bnq + 0] = to_tf32(bv0.x);
        Bs[buf][bkr][bnq + 1] = to_tf32(bv0.y);
        Bs[buf][bkr][bnq + 2] = to_tf32(bv0.z);
        Bs[buf][bkr][bnq + 3] = to_tf32(bv0.w);
        Bs[buf][bkr][bnq + 4] = to_tf32(bv1.x);
        Bs[buf][bkr][bnq + 5] = to_tf32(bv1.y);
        Bs[buf][bkr][bnq + 6] = to_tf32(bv1.z);
        Bs[buf][bkr][bnq + 7] = to_tf32(bv1.w);

        if (kt + 1 < KT) {
            Ap += 16;
            Wp += (long long)16 * N;
            av0 = *(const float4*)Ap;
            av1 = *(const float4*)(Ap + 4);
            if (nok) {
                bv0 = *(const float4*)Wp;
                bv1 = *(const float4*)(Wp + 4);
            }
        }

        __syncthreads();

        #pragma unroll
        for (int ks = 0; ks < 2; ks++) {
            int ko = ks * 8;
            uint32_t af[4][4], bf[4][2];
            uint32_t abase = smem_u32(&As[buf][lrow][ko + lcol]);
            #pragma unroll
            for (int i = 0; i < 4; i++)
                ldsm_x4(af[i], abase + (uint32_t)(i * 16 * 20 * 4));
            #pragma unroll
            for (int j = 0; j < 4; j++) {
                int nc = wn + j * 8 + (lane >> 2);
                int kr = ko + (lane & 3);
                bf[j][0] = __float_as_uint(Bs[buf][kr][nc]);
                bf[j][1] = __float_as_uint(Bs[buf][kr + 4][nc]);
            }
            #pragma unroll
            for (int i = 0; i < 4; i++)
                #pragma unroll
                for (int j = 0; j < 4; j++)
                    mma_tf32(acc[i][j], af[i], bf[j]);
        }
    }

    #pragma unroll
    for (int i = 0; i < 4; i++) {
        long long r0 = m0 + wm + i * 16 + (lane >> 2);
        long long r1 = r0 + 8;
        #pragma unroll
        for (int j = 0; j < 4; j++) {
            int cn = n0 + wn + j * 8 + (lane & 3) * 2;
            if (cn >= N) continue;
            float v00 = acc[i][j][0], v01 = acc[i][j][1];
            float v10 = acc[i][j][2], v11 = acc[i][j][3];
            if (bias) {
                float b0 = bias[cn], b1 = bias[cn + 1];
                v00 += b0; v01 += b1; v10 += b0; v11 += b1;
            }
            if (ACT == 1) {
                v00 = fmaxf(v00, 0.f); v01 = fmaxf(v01, 0.f);
                v10 = fmaxf(v10, 0.f); v11 = fmaxf(v11, 0.f);
            }
            if (ACT == 2) {
                v00 = 0.5f * v00 * (1.f + erff(v00 * 0.70710678118654752f));
                v01 = 0.5f * v01 * (1.f + erff(v01 * 0.70710678118654752f));
                v10 = 0.5f * v10 * (1.f + erff(v10 * 0.70710678118654752f));
                v11 = 0.5f * v11 * (1.f + erff(v11 * 0.70710678118654752f));
            }
            if (RES) {
                v00 += Rp[r0 * N + cn]; v01 += Rp[r0 * N + cn + 1];
                v10 += Rp[r1 * N + cn]; v11 += Rp[r1 * N + cn + 1];
            }
            float2 o0 = {v00, v01}, o1 = {v10, v11};
            *(float2*)&C[r0 * N + cn] = o0;
            *(float2*)&C[r1 * N + cn] = o1;
        }
    }
}

// ---------------------------------------------------------------------------
// u-GEMM with fused logits epilogue.
// Per (bh=z, vblk=by, nblk=bx): acc = scores[bh][128v x 512q] @ la[b][512q x 128d]
// then lpart[bh][vblk][n0+d] = sum_v ga[b][v0+v][n0+d] * acc[v][d]
// No u materialization.
// ---------------------------------------------------------------------------
__global__ __launch_bounds__(256, 2)
void ugemm_tc(const float* __restrict__ scores, const float* __restrict__ la,
              const float* __restrict__ ga, float* __restrict__ lpart)
{
    int z = blockIdx.z;                   // bh
    int b = z >> 2;
    const float* A = scores + (long long)z * 512 * 512;
    const float* W = la + (long long)b * 512 * DIM;
    const float* gab = ga + (long long)b * 512 * DIM;

    __shared__ __align__(16) float As[2][128][20];
    __shared__ __align__(16) float Bs[2][16][136];

    int m0 = blockIdx.y * 128, n0 = blockIdx.x * 128;
    int tid = threadIdx.x;
    int warp = tid >> 5, lane = tid & 31;
    int wm = (warp >> 2) * 64;
    int wn = (warp & 3) * 32;

    float acc[4][4][4];
    #pragma unroll
    for (int i = 0; i < 4; i++)
        #pragma unroll
        for (int j = 0; j < 4; j++)
            #pragma unroll
            for (int r = 0; r < 4; r++) acc[i][j][r] = 0.f;

    int arow = tid >> 1, akq = (tid & 1) * 8;
    const float* Ap = A + (long long)(m0 + arow) * 512 + akq;
    int bkr = tid >> 4, bnq = (tid & 15) * 8;
    const float* Wp = W + (long long)bkr * DIM + n0 + bnq;

    int lrow = wm + (lane & 15);
    int lcol = (lane >> 4) * 4;

    float4 av0 = *(const float4*)Ap;
    float4 av1 = *(const float4*)(Ap + 4);
    float4 bv0 = *(const float4*)Wp;
    float4 bv1 = *(const float4*)(Wp + 4);

    const int KT = 512 / 16;
    for (int kt = 0; kt < KT; kt++) {
        int buf = kt & 1;
        As[buf][arow][akq + 0] = to_tf32(av0.x);
        As[buf][arow][akq + 1] = to_tf32(av0.y);
        As[buf][arow][akq + 2] = to_tf32(av0.z);
        As[buf][arow][akq + 3] = to_tf32(av0.w);
        As[buf][arow][akq + 4] = to_tf32(av1.x);
        As[buf][arow][akq + 5] = to_tf32(av1.y);
        As[buf][arow][akq + 6] = to_tf32(av1.z);
        As[buf][arow][akq + 7] = to_tf32(av1.w);
        Bs[buf][bkr][bnq + 0] = to_tf32(bv0.x);
        Bs[buf][bkr][bnq + 1] = to_tf32(bv0.y);
        Bs[buf][bkr][bnq + 2] = to_tf32(bv0.z);
        Bs[buf][bkr][bnq + 3] = to_tf32(bv0.w);
        Bs[buf][bkr][bnq + 4] = to_tf32(bv1.x);
        Bs[buf][bkr][bnq + 5] = to_tf32(bv1.y);
        Bs[buf][bkr][bnq + 6] = to_tf32(bv1.z);
        Bs[buf][bkr][bnq + 7] = to_tf32(bv1.w);

        if (kt + 1 < KT) {
            Ap += 16;
            Wp += (long long)16 * DIM;
            av0 = *(const float4*)Ap;
            av1 = *(const float4*)(Ap + 4);
            bv0 = *(const float4*)Wp;
            bv1 = *(const float4*)(Wp + 4);
        }
        __syncthreads();

        #pragma unroll
        for (int ks = 0; ks < 2; ks++) {
            int ko = ks * 8;
            uint32_t af[4][4], bf[4][2];
            uint32_t abase = smem_u32(&As[buf][lrow][ko + lcol]);
            #pragma unroll
            for (int i = 0; i < 4; i++)
                ldsm_x4(af[i], abase + (uint32_t)(i * 16 * 20 * 4));
            #pragma unroll
            for (int j = 0; j < 4; j++) {
                int nc = wn + j * 8 + (lane >> 2);
                int kr = ko + (lane & 3);
                bf[j][0] = __float_as_uint(Bs[buf][kr][nc]);
                bf[j][1] = __float_as_uint(Bs[buf][kr + 4][nc]);
            }
            #pragma unroll
            for (int i = 0; i < 4; i++)
                #pragma unroll
                for (int j = 0; j < 4; j++)
                    mma_tf32(acc[i][j], af[i], bf[j]);
        }
    }

    // ---- fused logits epilogue ----
    float* gs = (float*)As;   // reuse: [32][132] chunk of ga tile
    float colacc[4][2];
    #pragma unroll
    for (int j = 0; j < 4; j++) { colacc[j][0] = 0.f; colacc[j][1] = 0.f; }

    for (int c = 0; c < 4; c++) {
        __syncthreads();
        #pragma unroll
        for (int it = 0; it < 4; it++) {
            int e = tid + 256 * it;          // 0..1023 float4s
            int row = e >> 5;                // 0..31
            int c4 = (e & 31) * 4;           // 0..124
            *(float4*)&gs[row * 132 + c4] =
                *(const float4*)&gab[(long long)(m0 + c * 32 + row) * DIM + n0 + c4];
        }
        __syncthreads();
        #pragma unroll
        for (int i = 0; i < 4; i++) {
            if (((wm + i * 16) >> 5) != c) continue;
            int lr0 = wm + i * 16 + (lane >> 2) - c * 32;   // 0..23
            #pragma unroll
            for (int j = 0; j < 4; j++) {
                int cn = wn + j * 8 + (lane & 3) * 2;       // 0..126
                colacc[j][0] += acc[i][j][0] * gs[lr0 * 132 + cn];
                colacc[j][1] += acc[i][j][1] * gs[lr0 * 132 + cn + 1];
                colacc[j][0] += acc[i][j][2] * gs[(lr0 + 8) * 132 + cn];
                colacc[j][1] += acc[i][j][3] * gs[(lr0 + 8) * 132 + cn + 1];
            }
        }
    }

    // reduce across lanes sharing the same columns (stride 4)
    #pragma unroll
    for (int o = 4; o < 32; o <<= 1)
        #pragma unroll
        for (int j = 0; j < 4; j++) {
            colacc[j][0] += __shfl_down_sync(0xffffffffu, colacc[j][0], o);
            colacc[j][1] += __shfl_down_sync(0xffffffffu, colacc[j][1], o);
        }

    float* red = (float*)Bs;   // reuse: [2][128]
    __syncthreads();
    if (lane < 4) {
        #pragma unroll
        for (int j = 0; j < 4; j++) {
            red[(warp >> 2) * 128 + wn + j * 8 + lane * 2]     = colacc[j][0];
            red[(warp >> 2) * 128 + wn + j * 8 + lane * 2 + 1] = colacc[j][1];
        }
    }
    __syncthreads();
    if (tid < 128)
        lpart[((long long)z * 4 + blockIdx.y) * 384 + n0 + tid] = red[tid] + red[128 + tid];
}

// ---------------------------------------------------------------------------
// Cross scores via TF32 MMA, double-buffered, ldmatrix A-frags.
// ---------------------------------------------------------------------------
__global__ __launch_bounds__(256, 2)
void cross_tc(const float* __restrict__ qh, const float* __restrict__ kh,
              const float* __restrict__ att_bias, const int* __restrict__ mask,
              float* __restrict__ scores)
{
    int bh = blockIdx.z;
    int b = bh >> 2, h = bh & 3;
    const float* Ab = qh + (long long)b * 512 * DIM + h * DH;
    const float* Bb = kh + (long long)b * 512 * DIM + h * DH;

    __shared__ __align__(16) float As[2][128][20];
    __shared__ __align__(16) float Bs[2][16][136];

    int v0 = blockIdx.y * 128, q0 = blockIdx.x * 128;
    int tid = threadIdx.x;
    int warp = tid >> 5, lane = tid & 31;
    int wm = (warp >> 2) * 64;
    int wn = (warp & 3) * 32;

    float acc[4][4][4];
    #pragma unroll
    for (int i = 0; i < 4; i++)
        #pragma unroll
        for (int j = 0; j < 4; j++)
            #pragma unroll
            for (int r = 0; r < 4; r++) acc[i][j][r] = 0.f;

    int arow = tid >> 1, akq = (tid & 1) * 8;
    const float* Ap = Ab + (long long)(v0 + arow) * DIM + akq;
    const float* Bp = Bb + (long long)(q0 + arow) * DIM + akq;

    int lrow = wm + (lane & 15);
    int lcol = (lane >> 4) * 4;

    float4 av0 = *(const float4*)Ap;
    float4 av1 = *(const float4*)(Ap + 4);
    float4 bv0 = *(const float4*)Bp;
    float4 bv1 = *(const float4*)(Bp + 4);

    const int KT = DH / 16;   // 6
    for (int kt = 0; kt < KT; kt++) {
        int buf = kt & 1;
        As[buf][arow][akq + 0] = to_tf32(av0.x);
        As[buf][arow][akq + 1] = to_tf32(av0.y);
        As[buf][arow][akq + 2] = to_tf32(av0.z);
        As[buf][arow][akq + 3] = to_tf32(av0.w);
        As[buf][arow][akq + 4] = to_tf32(av1.x);
        As[buf][arow][akq + 5] = to_tf32(av1.y);
        As[buf][arow][akq + 6] = to_tf32(av1.z);
        As[buf][arow][akq + 7] = to_tf32(av1.w);
        Bs[buf][akq + 0][arow] = to_tf32(bv0.x);
        Bs[buf][akq + 1][arow] = to_tf32(bv0.y);
        Bs[buf][akq + 2][arow] = to_tf32(bv0.z);
        Bs[buf][akq + 3][arow] = to_tf32(bv0.w);
        Bs[buf][akq + 4][arow] = to_tf32(bv1.x);
        Bs[buf][akq + 5][arow] = to_tf32(bv1.y);
        Bs[buf][akq + 6][arow] = to_tf32(bv1.z);
        Bs[buf][akq + 7][arow] = to_tf32(bv1.w);

        if (kt + 1 < KT) {
            Ap += 16; Bp += 16;
            av0 = *(const float4*)Ap;
            av1 = *(const float4*)(Ap + 4);
            bv0 = *(const float4*)Bp;
            bv1 = *(const float4*)(Bp + 4);
        }
        __syncthreads();

        #pragma unroll
        for (int ks = 0; ks < 2; ks++) {
            int ko = ks * 8;
            uint32_t af[4][4], bf[4][2];
            uint32_t abase = smem_u32(&As[buf][lrow][ko + lcol]);
            #pragma unroll
            for (int i = 0; i < 4; i++)
                ldsm_x4(af[i], abase + (uint32_t)(i * 16 * 20 * 4));
            #pragma unroll
            for (int j = 0; j < 4; j++) {
                int nc = wn + j * 8 + (lane >> 2);
                int kr = ko + (lane & 3);
                bf[j][0] = __float_as_uint(Bs[buf][kr][nc]);
                bf[j][1] = __float_as_uint(Bs[buf][kr + 4][nc]);
            }
            #pragma unroll
            for (int i = 0; i < 4; i++)
                #pragma unroll
                for (int j = 0; j < 4; j++)
                    mma_tf32(acc[i][j], af[i], bf[j]);
        }
    }

    const float scale = 0.10206207261596575f; // 1/sqrt(96)
    float biash = att_bias[h];
    float* out = scores + (long long)bh * 512 * 512;
    #pragma unroll
    for (int i = 0; i < 4; i++) {
        int va = v0 + wm + i * 16 + (lane >> 2);
        int vb = va + 8;
        bool ma = (mask[b * 512 + va] != 0);
        bool mb = (mask[b * 512 + vb] != 0);
        #pragma unroll
        for (int j = 0; j < 4; j++) {
            int cq = q0 + wn + j * 8 + (lane & 3) * 2;
            float2 oa, ob;
            oa.x = ma ? 0.f : (acc[i][j][0] * scale + biash);
            oa.y = ma ? 0.f : (acc[i][j][1] * scale + biash);
            ob.x = mb ? 0.f : (acc[i][j][2] * scale + biash);
            ob.y = mb ? 0.f : (acc[i][j][3] * scale + biash);
            *(float2*)&out[(long long)va * 512 + cq] = oa;
            *(float2*)&out[(long long)vb * 512 + cq] = ob;
        }
    }
}

// ---------------------------------------------------------------------------
// Flash self-attention (fp32): out = softmax(QK^T/sqrt(32)) @ V
// ---------------------------------------------------------------------------
__global__ __launch_bounds__(256, 2)
void flash_attn_k(const float* __restrict__ qkv, float* __restrict__ out)
{
    int bh = blockIdx.y;
    int b = bh / TH, h = bh % TH;
    int i0 = blockIdx.x * 64;
    const float* base = qkv + (long long)b * 512 * 288;
    const float* qb = base + h * 32;
    const float* kb = base + 96 + h * 32;
    const float* vb = base + 192 + h * 32;

    __shared__ float qs[64][36];
    __shared__ float ks[64][36];
    __shared__ float vs[64][36];
    __shared__ float ps[64][65];

    int tid = threadIdx.x;
    int r = tid >> 2, tq = tid & 3;

    for (int e = tid; e < 512; e += 256) {
        int row = e >> 3, c4 = (e & 7) * 4;
        *(float4*)&qs[row][c4] = *(const float4*)&qb[(long long)(i0 + row) * 288 + c4];
    }
    __syncthreads();
    float q[32];
    #pragma unroll
    for (int i = 0; i < 8; i++) *(float4*)&q[i * 4] = *(const float4*)&qs[r][i * 4];

    float O[8] = {};
    float mrow = -INFINITY, lrow = 0.f;
    const float scale = 0.1767766952966369f;

    for (int j0 = 0; j0 < 512; j0 += 64) {
        __syncthreads();
        for (int e = tid; e < 512; e += 256) {
            int row = e >> 3, c4 = (e & 7) * 4;
            *(float4*)&ks[row][c4] = *(const float4*)&kb[(long long)(j0 + row) * 288 + c4];
            *(float4*)&vs[row][c4] = *(const float4*)&vb[(long long)(j0 + row) * 288 + c4];
        }
        __syncthreads();

        float s[16];
        #pragma unroll
        for (int jj = 0; jj < 16; jj++) {
            int j = jj * 4 + tq;
            float a = 0.f;
            #pragma unroll
            for (int d4 = 0; d4 < 8; d4++) {
                float4 kk = *(const float4*)&ks[j][d4 * 4];
                a += q[d4*4+0]*kk.x + q[d4*4+1]*kk.y + q[d4*4+2]*kk.z + q[d4*4+3]*kk.w;
            }
            s[jj] = a * scale;
        }
        float smax = s[0];
        #pragma unroll
        for (int jj = 1; jj < 16; jj++) smax = fmaxf(smax, s[jj]);
        #pragma unroll
        for (int o = 1; o < 4; o <<= 1)
            smax = fmaxf(smax, __shfl_xor_sync(0xffffffffu, smax, o));
        float mnew = fmaxf(mrow, smax);
        float corr = __expf(mrow - mnew);
        float psum = 0.f;
        #pragma unroll
        for (int jj = 0; jj < 16; jj++) {
            float p = __expf(s[jj] - mnew);
            ps[r][jj * 4 + tq] = p;
            psum += p;
        }
        #pragma unroll
        for (int o = 1; o < 4; o <<= 1)
            psum += __shfl_xor_sync(0xffffffffu, psum, o);
        lrow = lrow * corr + psum;
        mrow = mnew;
        #pragma unroll
        for (int d = 0; d < 8; d++) O[d] *= corr;
        __syncwarp();

        int d0 = tq * 8;
        #pragma unroll 8
        for (int j = 0; j < 64; j++) {
            float pj = ps[r][j];
            float4 v0 = *(const float4*)&vs[j][d0];
            float4 v1 = *(const float4*)&vs[j][d0 + 4];
            O[0] += pj * v0.x; O[1] += pj * v0.y; O[2] += pj * v0.z; O[3] += pj * v0.w;
            O[4] += pj * v1.x; O[5] += pj * v1.y; O[6] += pj * v1.z; O[7] += pj * v1.w;
        }
    }

    float inv = 1.f / lrow;
    float* ob = out + (long long)(b * 512 + i0 + r) * 96 + h * 32 + tq * 8;
    float4 o0 = {O[0]*inv, O[1]*inv, O[2]*inv, O[3]*inv};
    float4 o1 = {O[4]*inv, O[5]*inv, O[6]*inv, O[7]*inv};
    *(float4*)ob = o0;
    *(float4*)(ob + 4) = o1;
}

// ---------------------------------------------------------------------------
// mask / final head
// ---------------------------------------------------------------------------
__global__ void mask_k(const float* __restrict__ gf, int* __restrict__ mask)
{
    int gw = (blockIdx.x * blockDim.x + threadIdx.x) >> 5;
    int lane = threadIdx.x & 31;
    if (gw >= ROWS) return;
    const float* row = gf + (long long)gw * GD;
    float s = 0.f;
    for (int i = lane; i < GD; i += 32) s += fabsf(row[i]);
    #pragma unroll
    for (int o = 16; o > 0; o >>= 1) s += __shfl_down_sync(0xffffffffu, s, o);
    if (lane == 0) mask[gw] = (s == 0.0f) ? 1 : 0;
}

__global__ void final_k(const float* __restrict__ lpart,
                        const float* __restrict__ bn_g, const float* __restrict__ bn_b,
                        const float* __restrict__ bn_mean, const float* __restrict__ bn_var,
                        const float* __restrict__ Wf, const float* __restrict__ bf,
                        float* __restrict__ out)
{
    int b = blockIdx.x, t = threadIdx.x;
    float pooled = 0.f;
    const float* lb = lpart + (long long)b * 16 * 384;   // 4 heads x 4 vblks
    #pragma unroll
    for (int hv = 0; hv < 16; hv++) {
        const float* lp = lb + hv * 384 + t * 3;
        pooled += lp[0] + lp[1] + lp[2];
    }
    float bn = (pooled - bn_mean[t]) * rsqrtf(bn_var[t] + 1e-5f) * bn_g[t] + bn_b[t];
    __shared__ float sh[128];
    sh[t] = bn * Wf[t];
    __syncthreads();
    for (int s = 64; s > 0; s >>= 1) {
        if (t < s) sh[t] += sh[t + s];
        __syncthreads();
    }
    if (t == 0) out[b] = sh[0] + bf[0];
}

// ---------------------------------------------------------------------------
// Host side
// ---------------------------------------------------------------------------
struct TrWeights {
    const float *ln1_g, *ln1_b, *Wqkv, *Wo, *bo, *ln2_g, *ln2_b, *W1, *b1, *W2, *b2;
};

static void run_transformer(float* x, float* lnstat, float* qkv, float* attnout,
                            float* ff, const TrWeights& w)
{
    lnstats_k<<<ROWS / 8, 256>>>(x, lnstat);
    gemm_tc<0, false, true><<<dim3(3, 128, 1), 256>>>(x, w.Wqkv, nullptr, nullptr, qkv,
                                                      lnstat, w.ln1_g, w.ln1_b,
                                                      ROWS, 288, 384, 0, 0, 0, 1);
    flash_attn_k<<<dim3(8, 96), 256>>>(qkv, attnout);
    gemm_tc<0, true, false><<<dim3(3, 128, 1), 256>>>(attnout, w.Wo, w.bo, x, x,
                                                      nullptr, nullptr, nullptr,
                                                      ROWS, 384, 96, 0, 0, 0, 1);
    lnstats_k<<<ROWS / 8, 256>>>(x, lnstat);
    gemm_tc<2, false, true><<<dim3(1, 128, 1), 256>>>(x, w.W1, w.b1, nullptr, ff,
                                                      lnstat, w.ln2_g, w.ln2_b,
                                                      ROWS, 128, 384, 0, 0, 0, 1);
    gemm_tc<0, true, false><<<dim3(3, 128, 1), 256>>>(ff, w.W2, w.b2, x, x,
                                                      nullptr, nullptr, nullptr,
                                                      ROWS, 384, 128, 0, 0, 0, 1);
}

extern "C" void kernel_launch(void* const* d_in, const int* in_sizes, int n_in,
                              void* d_out, int out_size)
{
    const float* global_feat = (const float*)d_in[0];
    const float* local_feat  = (const float*)d_in[1];
    const float* Wg   = (const float*)d_in[2];
    const float* bg   = (const float*)d_in[3];
    const float* Wl   = (const float*)d_in[4];
    const float* bl   = (const float*)d_in[5];
    TrWeights tw;
    tw.ln1_g = (const float*)d_in[6];
    tw.ln1_b = (const float*)d_in[7];
    tw.Wqkv  = (const float*)d_in[8];
    tw.Wo    = (const float*)d_in[9];
    tw.bo    = (const float*)d_in[10];
    tw.ln2_g = (const float*)d_in[11];
    tw.ln2_b = (const float*)d_in[12];
    tw.W1    = (const float*)d_in[13];
    tw.b1    = (const float*)d_in[14];
    tw.W2    = (const float*)d_in[15];
    tw.b2    = (const float*)d_in[16];
    const float* Wq       = (const float*)d_in[17];
    const float* Wk       = (const float*)d_in[18];
    const float* att_bias = (const float*)d_in[19];
    const float* bn_g     = (const float*)d_in[20];
    const float* bn_b     = (const float*)d_in[21];
    const float* bn_mean  = (const float*)d_in[22];
    const float* bn_var   = (const float*)d_in[23];
    const float* Wf       = (const float*)d_in[24];
    const float* bf       = (const float*)d_in[25];

    void *p;
    cudaGetSymbolAddress(&p, g_ga);      float* ga      = (float*)p;
    cudaGetSymbolAddress(&p, g_la);      float* la      = (float*)p;
    cudaGetSymbolAddress(&p, g_qkv);     float* qkv     = (float*)p;
    cudaGetSymbolAddress(&p, g_attnout); float* attnout = (float*)p;
    cudaGetSymbolAddress(&p, g_ff);      float* ff      = (float*)p;
    cudaGetSymbolAddress(&p, g_qh);      float* qh      = (float*)p;
    cudaGetSymbolAddress(&p, g_kh);      float* kh      = (float*)p;
    cudaGetSymbolAddress(&p, g_lpart);   float* lpart   = (float*)p;
    cudaGetSymbolAddress(&p, g_lnstat);  float* lnstat  = (float*)p;
    cudaGetSymbolAddress(&p, g_mask);    int*   mask    = (int*)p;

    float* out_scalar = (float*)d_out;
    float* scores = out_scalar + BATCH;

    // 1) Input projections (ReLU)
    gemm_tc<1, false, false><<<dim3(3, 128, 1), 256>>>(global_feat, Wg, bg, nullptr, ga,
                                                       nullptr, nullptr, nullptr,
                                                       ROWS, DIM, GD, 0, 0, 0, 1);
    gemm_tc<1, false, false><<<dim3(3, 128, 1), 256>>>(local_feat, Wl, bl, nullptr, la,
                                                       nullptr, nullptr, nullptr,
                                                       ROWS, DIM, LD, 0, 0, 0, 1);

    // 2) Shared-weight transformer on both streams
    run_transformer(ga, lnstat, qkv, attnout, ff, tw);
    run_transformer(la, lnstat, qkv, attnout, ff, tw);

    // 3) Cross q/k projections
    gemm_tc<0, false, false><<<dim3(3, 128, 1), 256>>>(ga, Wq, nullptr, nullptr, qh,
                                                       nullptr, nullptr, nullptr,
                                                       ROWS, DIM, DIM, 0, 0, 0, 1);
    gemm_tc<0, false, false><<<dim3(3, 128, 1), 256>>>(la, Wk, nullptr, nullptr, kh,
                                                       nullptr, nullptr, nullptr,
                                                       ROWS, DIM, DIM, 0, 0, 0, 1);

    // 4) Mask + cross scores (into d_out)
    mask_k<<<(ROWS * 32 + 255) / 256, 256>>>(global_feat, mask);
    cross_tc<<<dim3(4, 4, 128), 256>>>(qh, kh, att_bias, mask, scores);

    // 5) u-GEMM with fused logits reduction (no u materialization)
    ugemm_tc<<<dim3(3, 4, 128), 256>>>(scores, la, ga, lpart);

    // 6) head
    final_k<<<BATCH, 128>>>(lpart, bn_g, bn_b, bn_mean, bn_var, Wf, bf, out_scalar);
}

// round 11
// speedup vs baseline: 2.5176x; 1.0492x over previous
#include <cuda_runtime.h>
#include <math.h>
#include <stdint.h>

// ---------------------------------------------------------------------------
// Problem constants
// ---------------------------------------------------------------------------
#define BATCH 32
#define GD    512
#define LD    256
#define DIM   384
#define TH    3
#define THD   32
#define HOUT  4
#define DH    96
#define HID   128
#define ROWS  (BATCH * 512)   // 16384

// ---------------------------------------------------------------------------
// Scratch (both streams batched: [0]=global, [1]=local)
// ---------------------------------------------------------------------------
__device__ float g_act[2 * ROWS * DIM];
__device__ float g_qkv[2 * ROWS * 288];
__device__ float g_attnout[2 * ROWS * 96];
__device__ float g_ff[2 * ROWS * 128];
__device__ float g_qh[ROWS * DIM];
__device__ float g_kh[ROWS * DIM];
__device__ float g_lpart[128 * 4 * 384];
__device__ float g_lnstat[2 * ROWS * 2];
__device__ int   g_mask[ROWS];

// ---------------------------------------------------------------------------
// TF32 helpers
// ---------------------------------------------------------------------------
__device__ __forceinline__ float to_tf32(float x) {
    uint32_t u;
    asm("cvt.rna.tf32.f32 %0, %1;" : "=r"(u) : "f"(x));
    return __uint_as_float(u);
}

__device__ __forceinline__ void mma_tf32(float* d, const uint32_t* a, const uint32_t* b) {
    asm volatile(
        "mma.sync.aligned.m16n8k8.row.col.f32.tf32.tf32.f32 "
        "{%0,%1,%2,%3}, {%4,%5,%6,%7}, {%8,%9}, {%0,%1,%2,%3};"
        : "+f"(d[0]), "+f"(d[1]), "+f"(d[2]), "+f"(d[3])
        : "r"(a[0]), "r"(a[1]), "r"(a[2]), "r"(a[3]), "r"(b[0]), "r"(b[1]));
}

// ---------------------------------------------------------------------------
// Row LN stats: stat[row] = {mean, rstd}. One warp per row.
// ---------------------------------------------------------------------------
__global__ void lnstats_k(const float* __restrict__ x, float* __restrict__ stat)
{
    int row = blockIdx.x * 8 + (threadIdx.x >> 5);
    int lane = threadIdx.x & 31;
    const float* xr = x + (long long)row * DIM;
    float s = 0.f, s2 = 0.f;
    #pragma unroll
    for (int i = 0; i < 12; i++) {
        float v = xr[lane + 32 * i];
        s += v; s2 += v * v;
    }
    #pragma unroll
    for (int o = 16; o > 0; o >>= 1) {
        s  += __shfl_xor_sync(0xffffffffu, s, o);
        s2 += __shfl_xor_sync(0xffffffffu, s2, o);
    }
    if (lane == 0) {
        float mean = s * (1.f / DIM);
        float var = s2 * (1.f / DIM) - mean * mean;
        stat[row * 2] = mean;
        stat[row * 2 + 1] = rsqrtf(var + 1e-5f);
    }
}

// ---------------------------------------------------------------------------
// TF32 GEMM, 256 thr, double-buffered, scalar frag loads (conflict-free).
// C = act((LNA ? LN(A) : A) @ W + bias) (+ residual)
// Batched via blockIdx.z: A += z*sA, C += z*sC, res += z*sC,
//   W += (z/wdiv)*sW, lnstat += z*sLn.
// ---------------------------------------------------------------------------
template<int ACT, bool RES, bool LNA>
__global__ __launch_bounds__(256, 2)
void gemm_tc(const float* __restrict__ A, const float* __restrict__ W,
             const float* __restrict__ bias, const float* __restrict__ res,
             float* __restrict__ C,
             const float* __restrict__ lnstat, const float* __restrict__ lng,
             const float* __restrict__ lnb,
             int M, int N, int K,
             long long sA, long long sW, long long sC, long long sLn, int wdiv)
{
    int z = blockIdx.z;
    A += (long long)z * sA;
    C += (long long)z * sC;
    W += (long long)(z / wdiv) * sW;
    if (LNA) lnstat += (long long)z * sLn;
    const float* Rp = RES ? (res + (long long)z * sC) : nullptr;

    __shared__ __align__(16) float As[2][128][20];
    __shared__ __align__(16) float Bs[2][16][136];

    int m0 = blockIdx.y * 128, n0 = blockIdx.x * 128;
    int tid = threadIdx.x;
    int warp = tid >> 5, lane = tid & 31;
    int wm = (warp >> 2) * 64;
    int wn = (warp & 3) * 32;

    float acc[4][4][4];
    #pragma unroll
    for (int i = 0; i < 4; i++)
        #pragma unroll
        for (int j = 0; j < 4; j++)
            #pragma unroll
            for (int r = 0; r < 4; r++) acc[i][j][r] = 0.f;

    int arow = tid >> 1, akq = (tid & 1) * 8;
    const float* Ap = A + (long long)(m0 + arow) * K + akq;
    int bkr = tid >> 4, bnq = (tid & 15) * 8;
    const float* Wp = W + (long long)bkr * N + n0 + bnq;
    bool nok = (n0 + bnq < N);

    float mean = 0.f, rstd = 0.f;
    if (LNA) {
        mean = lnstat[(m0 + arow) * 2];
        rstd = lnstat[(m0 + arow) * 2 + 1];
    }

    float4 av0 = *(const float4*)Ap;
    float4 av1 = *(const float4*)(Ap + 4);
    float4 bv0 = nok ? *(const float4*)Wp       : make_float4(0, 0, 0, 0);
    float4 bv1 = nok ? *(const float4*)(Wp + 4) : make_float4(0, 0, 0, 0);

    int KT = K >> 4;
    for (int kt = 0; kt < KT; kt++) {
        int buf = kt & 1;
        if (LNA) {
            int kg = kt * 16 + akq;
            float4 g0 = *(const float4*)&lng[kg];
            float4 g1 = *(const float4*)&lng[kg + 4];
            float4 b0 = *(const float4*)&lnb[kg];
            float4 b1 = *(const float4*)&lnb[kg + 4];
            As[buf][arow][akq + 0] = to_tf32((av0.x - mean) * rstd * g0.x + b0.x);
            As[buf][arow][akq + 1] = to_tf32((av0.y - mean) * rstd * g0.y + b0.y);
            As[buf][arow][akq + 2] = to_tf32((av0.z - mean) * rstd * g0.z + b0.z);
            As[buf][arow][akq + 3] = to_tf32((av0.w - mean) * rstd * g0.w + b0.w);
            As[buf][arow][akq + 4] = to_tf32((av1.x - mean) * rstd * g1.x + b1.x);
            As[buf][arow][akq + 5] = to_tf32((av1.y - mean) * rstd * g1.y + b1.y);
            As[buf][arow][akq + 6] = to_tf32((av1.z - mean) * rstd * g1.z + b1.z);
            As[buf][arow][akq + 7] = to_tf32((av1.w - mean) * rstd * g1.w + b1.w);
        } else {
            As[buf][arow][akq + 0] = to_tf32(av0.x);
            As[buf][arow][akq + 1] = to_tf32(av0.y);
            As[buf][arow][akq + 2] = to_tf32(av0.z);
            As[buf][arow][akq + 3] = to_tf32(av0.w);
            As[buf][arow][akq + 4] = to_tf32(av1.x);
            As[buf][arow][akq + 5] = to_tf32(av1.y);
            As[buf][arow][akq + 6] = to_tf32(av1.z);
            As[buf][arow][akq + 7] = to_tf32(av1.w);
        }
        Bs[buf][bkr][bnq + 0] = to_tf32(bv0.x);
        Bs[buf][bkr][bnq + 1] = to_tf32(bv0.y);
        Bs[buf][bkr][bnq + 2] = to_tf32(bv0.z);
        Bs[buf][bkr][bnq + 3] = to_tf32(bv0.w);
        Bs[buf][bkr][bnq + 4] = to_tf32(bv1.x);
        Bs[buf][bkr][bnq + 5] = to_tf32(bv1.y);
        Bs[buf][bkr][bnq + 6] = to_tf32(bv1.z);
        Bs[buf][bkr][bnq + 7] = to_tf32(bv1.w);

        if (kt + 1 < KT) {
            Ap += 16;
            Wp += (long long)16 * N;
            av0 = *(const float4*)Ap;
            av1 = *(const float4*)(Ap + 4);
            if (nok) {
                bv0 = *(const float4*)Wp;
                bv1 = *(const float4*)(Wp + 4);
            }
        }

        __syncthreads();

        #pragma unroll
        for (int ks = 0; ks < 2; ks++) {
            int ko = ks * 8;
            uint32_t af[4][4], bf[4][2];
            #pragma unroll
            for (int i = 0; i < 4; i++) {
                int mr = wm + i * 16 + (lane >> 2);
                int kc = ko + (lane & 3);
                af[i][0] = __float_as_uint(As[buf][mr][kc]);
                af[i][1] = __float_as_uint(As[buf][mr + 8][kc]);
                af[i][2] = __float_as_uint(As[buf][mr][kc + 4]);
                af[i][3] = __float_as_uint(As[buf][mr + 8][kc + 4]);
            }
            #pragma unroll
            for (int j = 0; j < 4; j++) {
                int nc = wn + j * 8 + (lane >> 2);
                int kr = ko + (lane & 3);
                bf[j][0] = __float_as_uint(Bs[buf][kr][nc]);
                bf[j][1] = __float_as_uint(Bs[buf][kr + 4][nc]);
            }
            #pragma unroll
            for (int i = 0; i < 4; i++)
                #pragma unroll
                for (int j = 0; j < 4; j++)
                    mma_tf32(acc[i][j], af[i], bf[j]);
        }
    }

    #pragma unroll
    for (int i = 0; i < 4; i++) {
        long long r0 = m0 + wm + i * 16 + (lane >> 2);
        long long r1 = r0 + 8;
        #pragma unroll
        for (int j = 0; j < 4; j++) {
            int cn = n0 + wn + j * 8 + (lane & 3) * 2;
            if (cn >= N) continue;
            float v00 = acc[i][j][0], v01 = acc[i][j][1];
            float v10 = acc[i][j][2], v11 = acc[i][j][3];
            if (bias) {
                float b0 = bias[cn], b1 = bias[cn + 1];
                v00 += b0; v01 += b1; v10 += b0; v11 += b1;
            }
            if (ACT == 1) {
                v00 = fmaxf(v00, 0.f); v01 = fmaxf(v01, 0.f);
                v10 = fmaxf(v10, 0.f); v11 = fmaxf(v11, 0.f);
            }
            if (ACT == 2) {
                v00 = 0.5f * v00 * (1.f + erff(v00 * 0.70710678118654752f));
                v01 = 0.5f * v01 * (1.f + erff(v01 * 0.70710678118654752f));
                v10 = 0.5f * v10 * (1.f + erff(v10 * 0.70710678118654752f));
                v11 = 0.5f * v11 * (1.f + erff(v11 * 0.70710678118654752f));
            }
            if (RES) {
                v00 += Rp[r0 * N + cn]; v01 += Rp[r0 * N + cn + 1];
                v10 += Rp[r1 * N + cn]; v11 += Rp[r1 * N + cn + 1];
            }
            float2 o0 = {v00, v01}, o1 = {v10, v11};
            *(float2*)&C[r0 * N + cn] = o0;
            *(float2*)&C[r1 * N + cn] = o1;
        }
    }
}

// ---------------------------------------------------------------------------
// u-GEMM with fused logits epilogue (scalar frag loads).
// ---------------------------------------------------------------------------
__global__ __launch_bounds__(256, 2)
void ugemm_tc(const float* __restrict__ scores, const float* __restrict__ la,
              const float* __restrict__ ga, float* __restrict__ lpart)
{
    int z = blockIdx.z;                   // bh
    int b = z >> 2;
    const float* A = scores + (long long)z * 512 * 512;
    const float* W = la + (long long)b * 512 * DIM;
    const float* gab = ga + (long long)b * 512 * DIM;

    __shared__ __align__(16) float As[2][128][20];
    __shared__ __align__(16) float Bs[2][16][136];

    int m0 = blockIdx.y * 128, n0 = blockIdx.x * 128;
    int tid = threadIdx.x;
    int warp = tid >> 5, lane = tid & 31;
    int wm = (warp >> 2) * 64;
    int wn = (warp & 3) * 32;

    float acc[4][4][4];
    #pragma unroll
    for (int i = 0; i < 4; i++)
        #pragma unroll
        for (int j = 0; j < 4; j++)
            #pragma unroll
            for (int r = 0; r < 4; r++) acc[i][j][r] = 0.f;

    int arow = tid >> 1, akq = (tid & 1) * 8;
    const float* Ap = A + (long long)(m0 + arow) * 512 + akq;
    int bkr = tid >> 4, bnq = (tid & 15) * 8;
    const float* Wp = W + (long long)bkr * DIM + n0 + bnq;

    float4 av0 = *(const float4*)Ap;
    float4 av1 = *(const float4*)(Ap + 4);
    float4 bv0 = *(const float4*)Wp;
    float4 bv1 = *(const float4*)(Wp + 4);

    const int KT = 512 / 16;
    for (int kt = 0; kt < KT; kt++) {
        int buf = kt & 1;
        As[buf][arow][akq + 0] = to_tf32(av0.x);
        As[buf][arow][akq + 1] = to_tf32(av0.y);
        As[buf][arow][akq + 2] = to_tf32(av0.z);
        As[buf][arow][akq + 3] = to_tf32(av0.w);
        As[buf][arow][akq + 4] = to_tf32(av1.x);
        As[buf][arow][akq + 5] = to_tf32(av1.y);
        As[buf][arow][akq + 6] = to_tf32(av1.z);
        As[buf][arow][akq + 7] = to_tf32(av1.w);
        Bs[buf][bkr][bnq + 0] = to_tf32(bv0.x);
        Bs[buf][bkr][bnq + 1] = to_tf32(bv0.y);
        Bs[buf][bkr][bnq + 2] = to_tf32(bv0.z);
        Bs[buf][bkr][bnq + 3] = to_tf32(bv0.w);
        Bs[buf][bkr][bnq + 4] = to_tf32(bv1.x);
        Bs[buf][bkr][bnq + 5] = to_tf32(bv1.y);
        Bs[buf][bkr][bnq + 6] = to_tf32(bv1.z);
        Bs[buf][bkr][bnq + 7] = to_tf32(bv1.w);

        if (kt + 1 < KT) {
            Ap += 16;
            Wp += (long long)16 * DIM;
            av0 = *(const float4*)Ap;
            av1 = *(const float4*)(Ap + 4);
            bv0 = *(const float4*)Wp;
            bv1 = *(const float4*)(Wp + 4);
        }
        __syncthreads();

        #pragma unroll
        for (int ks = 0; ks < 2; ks++) {
            int ko = ks * 8;
            uint32_t af[4][4], bf[4][2];
            #pragma unroll
            for (int i = 0; i < 4; i++) {
                int mr = wm + i * 16 + (lane >> 2);
                int kc = ko + (lane & 3);
                af[i][0] = __float_as_uint(As[buf][mr][kc]);
                af[i][1] = __float_as_uint(As[buf][mr + 8][kc]);
                af[i][2] = __float_as_uint(As[buf][mr][kc + 4]);
                af[i][3] = __float_as_uint(As[buf][mr + 8][kc + 4]);
            }
            #pragma unroll
            for (int j = 0; j < 4; j++) {
                int nc = wn + j * 8 + (lane >> 2);
                int kr = ko + (lane & 3);
                bf[j][0] = __float_as_uint(Bs[buf][kr][nc]);
                bf[j][1] = __float_as_uint(Bs[buf][kr + 4][nc]);
            }
            #pragma unroll
            for (int i = 0; i < 4; i++)
                #pragma unroll
                for (int j = 0; j < 4; j++)
                    mma_tf32(acc[i][j], af[i], bf[j]);
        }
    }

    // ---- fused logits epilogue ----
    float* gs = (float*)As;   // reuse: [32][132] chunk of ga tile
    float colacc[4][2];
    #pragma unroll
    for (int j = 0; j < 4; j++) { colacc[j][0] = 0.f; colacc[j][1] = 0.f; }

    for (int c = 0; c < 4; c++) {
        __syncthreads();
        #pragma unroll
        for (int it = 0; it < 4; it++) {
            int e = tid + 256 * it;
            int row = e >> 5;
            int c4 = (e & 31) * 4;
            *(float4*)&gs[row * 132 + c4] =
                *(const float4*)&gab[(long long)(m0 + c * 32 + row) * DIM + n0 + c4];
        }
        __syncthreads();
        #pragma unroll
        for (int i = 0; i < 4; i++) {
            if (((wm + i * 16) >> 5) != c) continue;
            int lr0 = wm + i * 16 + (lane >> 2) - c * 32;
            #pragma unroll
            for (int j = 0; j < 4; j++) {
                int cn = wn + j * 8 + (lane & 3) * 2;
                colacc[j][0] += acc[i][j][0] * gs[lr0 * 132 + cn];
                colacc[j][1] += acc[i][j][1] * gs[lr0 * 132 + cn + 1];
                colacc[j][0] += acc[i][j][2] * gs[(lr0 + 8) * 132 + cn];
                colacc[j][1] += acc[i][j][3] * gs[(lr0 + 8) * 132 + cn + 1];
            }
        }
    }

    #pragma unroll
    for (int o = 4; o < 32; o <<= 1)
        #pragma unroll
        for (int j = 0; j < 4; j++) {
            colacc[j][0] += __shfl_down_sync(0xffffffffu, colacc[j][0], o);
            colacc[j][1] += __shfl_down_sync(0xffffffffu, colacc[j][1], o);
        }

    float* red = (float*)Bs;
    __syncthreads();
    if (lane < 4) {
        #pragma unroll
        for (int j = 0; j < 4; j++) {
            red[(warp >> 2) * 128 + wn + j * 8 + lane * 2]     = colacc[j][0];
            red[(warp >> 2) * 128 + wn + j * 8 + lane * 2 + 1] = colacc[j][1];
        }
    }
    __syncthreads();
    if (tid < 128)
        lpart[((long long)z * 4 + blockIdx.y) * 384 + n0 + tid] = red[tid] + red[128 + tid];
}

// ---------------------------------------------------------------------------
// Cross scores via TF32 MMA, double-buffered, scalar frag loads.
// ---------------------------------------------------------------------------
__global__ __launch_bounds__(256, 2)
void cross_tc(const float* __restrict__ qh, const float* __restrict__ kh,
              const float* __restrict__ att_bias, const int* __restrict__ mask,
              float* __restrict__ scores)
{
    int bh = blockIdx.z;
    int b = bh >> 2, h = bh & 3;
    const float* Ab = qh + (long long)b * 512 * DIM + h * DH;
    const float* Bb = kh + (long long)b * 512 * DIM + h * DH;

    __shared__ __align__(16) float As[2][128][20];
    __shared__ __align__(16) float Bs[2][16][136];

    int v0 = blockIdx.y * 128, q0 = blockIdx.x * 128;
    int tid = threadIdx.x;
    int warp = tid >> 5, lane = tid & 31;
    int wm = (warp >> 2) * 64;
    int wn = (warp & 3) * 32;

    float acc[4][4][4];
    #pragma unroll
    for (int i = 0; i < 4; i++)
        #pragma unroll
        for (int j = 0; j < 4; j++)
            #pragma unroll
            for (int r = 0; r < 4; r++) acc[i][j][r] = 0.f;

    int arow = tid >> 1, akq = (tid & 1) * 8;
    const float* Ap = Ab + (long long)(v0 + arow) * DIM + akq;
    const float* Bp = Bb + (long long)(q0 + arow) * DIM + akq;

    float4 av0 = *(const float4*)Ap;
    float4 av1 = *(const float4*)(Ap + 4);
    float4 bv0 = *(const float4*)Bp;
    float4 bv1 = *(const float4*)(Bp + 4);

    const int KT = DH / 16;   // 6
    for (int kt = 0; kt < KT; kt++) {
        int buf = kt & 1;
        As[buf][arow][akq + 0] = to_tf32(av0.x);
        As[buf][arow][akq + 1] = to_tf32(av0.y);
        As[buf][arow][akq + 2] = to_tf32(av0.z);
        As[buf][arow][akq + 3] = to_tf32(av0.w);
        As[buf][arow][akq + 4] = to_tf32(av1.x);
        As[buf][arow][akq + 5] = to_tf32(av1.y);
        As[buf][arow][akq + 6] = to_tf32(av1.z);
        As[buf][arow][akq + 7] = to_tf32(av1.w);
        Bs[buf][akq + 0][arow] = to_tf32(bv0.x);
        Bs[buf][akq + 1][arow] = to_tf32(bv0.y);
        Bs[buf][akq + 2][arow] = to_tf32(bv0.z);
        Bs[buf][akq + 3][arow] = to_tf32(bv0.w);
        Bs[buf][akq + 4][arow] = to_tf32(bv1.x);
        Bs[buf][akq + 5][arow] = to_tf32(bv1.y);
        Bs[buf][akq + 6][arow] = to_tf32(bv1.z);
        Bs[buf][akq + 7][arow] = to_tf32(bv1.w);

        if (kt + 1 < KT) {
            Ap += 16; Bp += 16;
            av0 = *(const float4*)Ap;
            av1 = *(const float4*)(Ap + 4);
            bv0 = *(const float4*)Bp;
            bv1 = *(const float4*)(Bp + 4);
        }
        __syncthreads();

        #pragma unroll
        for (int ks = 0; ks < 2; ks++) {
            int ko = ks * 8;
            uint32_t af[4][4], bf[4][2];
            #pragma unroll
            for (int i = 0; i < 4; i++) {
                int mr = wm + i * 16 + (lane >> 2);
                int kc = ko + (lane & 3);
                af[i][0] = __float_as_uint(As[buf][mr][kc]);
                af[i][1] = __float_as_uint(As[buf][mr + 8][kc]);
                af[i][2] = __float_as_uint(As[buf][mr][kc + 4]);
                af[i][3] = __float_as_uint(As[buf][mr + 8][kc + 4]);
            }
            #pragma unroll
            for (int j = 0; j < 4; j++) {
                int nc = wn + j * 8 + (lane >> 2);
                int kr = ko + (lane & 3);
                bf[j][0] = __float_as_uint(Bs[buf][kr][nc]);
                bf[j][1] = __float_as_uint(Bs[buf][kr + 4][nc]);
            }
            #pragma unroll
            for (int i = 0; i < 4; i++)
                #pragma unroll
                for (int j = 0; j < 4; j++)
                    mma_tf32(acc[i][j], af[i], bf[j]);
        }
    }

    const float scale = 0.10206207261596575f; // 1/sqrt(96)
    float biash = att_bias[h];
    float* out = scores + (long long)bh * 512 * 512;
    #pragma unroll
    for (int i = 0; i < 4; i++) {
        int va = v0 + wm + i * 16 + (lane >> 2);
        int vb = va + 8;
        bool ma = (mask[b * 512 + va] != 0);
        bool mb = (mask[b * 512 + vb] != 0);
        #pragma unroll
        for (int j = 0; j < 4; j++) {
            int cq = q0 + wn + j * 8 + (lane & 3) * 2;
            float2 oa, ob;
            oa.x = ma ? 0.f : (acc[i][j][0] * scale + biash);
            oa.y = ma ? 0.f : (acc[i][j][1] * scale + biash);
            ob.x = mb ? 0.f : (acc[i][j][2] * scale + biash);
            ob.y = mb ? 0.f : (acc[i][j][3] * scale + biash);
            *(float2*)&out[(long long)va * 512 + cq] = oa;
            *(float2*)&out[(long long)vb * 512 + cq] = ob;
        }
    }
}

// ---------------------------------------------------------------------------
// Flash self-attention (fp32): out = softmax(QK^T/sqrt(32)) @ V
// bh spans 2*BATCH*TH = 192 (both streams).
// ---------------------------------------------------------------------------
__global__ __launch_bounds__(256, 2)
void flash_attn_k(const float* __restrict__ qkv, float* __restrict__ out)
{
    int bh = blockIdx.y;
    int b = bh / TH, h = bh % TH;
    int i0 = blockIdx.x * 64;
    const float* base = qkv + (long long)b * 512 * 288;
    const float* qb = base + h * 32;
    const float* kb = base + 96 + h * 32;
    const float* vb = base + 192 + h * 32;

    __shared__ float qs[64][36];
    __shared__ float ks[64][36];
    __shared__ float vs[64][36];
    __shared__ float ps[64][65];

    int tid = threadIdx.x;
    int r = tid >> 2, tq = tid & 3;

    for (int e = tid; e < 512; e += 256) {
        int row = e >> 3, c4 = (e & 7) * 4;
        *(float4*)&qs[row][c4] = *(const float4*)&qb[(long long)(i0 + row) * 288 + c4];
    }
    __syncthreads();
    float q[32];
    #pragma unroll
    for (int i = 0; i < 8; i++) *(float4*)&q[i * 4] = *(const float4*)&qs[r][i * 4];

    float O[8] = {};
    float mrow = -INFINITY, lrow = 0.f;
    const float scale = 0.1767766952966369f;

    for (int j0 = 0; j0 < 512; j0 += 64) {
        __syncthreads();
        for (int e = tid; e < 512; e += 256) {
            int row = e >> 3, c4 = (e & 7) * 4;
            *(float4*)&ks[row][c4] = *(const float4*)&kb[(long long)(j0 + row) * 288 + c4];
            *(float4*)&vs[row][c4] = *(const float4*)&vb[(long long)(j0 + row) * 288 + c4];
        }
        __syncthreads();

        float s[16];
        #pragma unroll
        for (int jj = 0; jj < 16; jj++) {
            int j = jj * 4 + tq;
            float a = 0.f;
            #pragma unroll
            for (int d4 = 0; d4 < 8; d4++) {
                float4 kk = *(const float4*)&ks[j][d4 * 4];
                a += q[d4*4+0]*kk.x + q[d4*4+1]*kk.y + q[d4*4+2]*kk.z + q[d4*4+3]*kk.w;
            }
            s[jj] = a * scale;
        }
        float smax = s[0];
        #pragma unroll
        for (int jj = 1; jj < 16; jj++) smax = fmaxf(smax, s[jj]);
        #pragma unroll
        for (int o = 1; o < 4; o <<= 1)
            smax = fmaxf(smax, __shfl_xor_sync(0xffffffffu, smax, o));
        float mnew = fmaxf(mrow, smax);
        float corr = __expf(mrow - mnew);
        float psum = 0.f;
        #pragma unroll
        for (int jj = 0; jj < 16; jj++) {
            float p = __expf(s[jj] - mnew);
            ps[r][jj * 4 + tq] = p;
            psum += p;
        }
        #pragma unroll
        for (int o = 1; o < 4; o <<= 1)
            psum += __shfl_xor_sync(0xffffffffu, psum, o);
        lrow = lrow * corr + psum;
        mrow = mnew;
        #pragma unroll
        for (int d = 0; d < 8; d++) O[d] *= corr;
        __syncwarp();

        int d0 = tq * 8;
        #pragma unroll 8
        for (int j = 0; j < 64; j++) {
            float pj = ps[r][j];
            float4 v0 = *(const float4*)&vs[j][d0];
            float4 v1 = *(const float4*)&vs[j][d0 + 4];
            O[0] += pj * v0.x; O[1] += pj * v0.y; O[2] += pj * v0.z; O[3] += pj * v0.w;
            O[4] += pj * v1.x; O[5] += pj * v1.y; O[6] += pj * v1.z; O[7] += pj * v1.w;
        }
    }

    float inv = 1.f / lrow;
    float* ob = out + (long long)(b * 512 + i0 + r) * 96 + h * 32 + tq * 8;
    float4 o0 = {O[0]*inv, O[1]*inv, O[2]*inv, O[3]*inv};
    float4 o1 = {O[4]*inv, O[5]*inv, O[6]*inv, O[7]*inv};
    *(float4*)ob = o0;
    *(float4*)(ob + 4) = o1;
}

// ---------------------------------------------------------------------------
// mask / final head
// ---------------------------------------------------------------------------
__global__ void mask_k(const float* __restrict__ gf, int* __restrict__ mask)
{
    int gw = (blockIdx.x * blockDim.x + threadIdx.x) >> 5;
    int lane = threadIdx.x & 31;
    if (gw >= ROWS) return;
    const float* row = gf + (long long)gw * GD;
    float s = 0.f;
    for (int i = lane; i < GD; i += 32) s += fabsf(row[i]);
    #pragma unroll
    for (int o = 16; o > 0; o >>= 1) s += __shfl_down_sync(0xffffffffu, s, o);
    if (lane == 0) mask[gw] = (s == 0.0f) ? 1 : 0;
}

__global__ void final_k(const float* __restrict__ lpart,
                        const float* __restrict__ bn_g, const float* __restrict__ bn_b,
                        const float* __restrict__ bn_mean, const float* __restrict__ bn_var,
                        const float* __restrict__ Wf, const float* __restrict__ bf,
                        float* __restrict__ out)
{
    int b = blockIdx.x, t = threadIdx.x;
    float pooled = 0.f;
    const float* lb = lpart + (long long)b * 16 * 384;
    #pragma unroll
    for (int hv = 0; hv < 16; hv++) {
        const float* lp = lb + hv * 384 + t * 3;
        pooled += lp[0] + lp[1] + lp[2];
    }
    float bn = (pooled - bn_mean[t]) * rsqrtf(bn_var[t] + 1e-5f) * bn_g[t] + bn_b[t];
    __shared__ float sh[128];
    sh[t] = bn * Wf[t];
    __syncthreads();
    for (int s = 64; s > 0; s >>= 1) {
        if (t < s) sh[t] += sh[t + s];
        __syncthreads();
    }
    if (t == 0) out[b] = sh[0] + bf[0];
}

// ---------------------------------------------------------------------------
// Host side
// ---------------------------------------------------------------------------
extern "C" void kernel_launch(void* const* d_in, const int* in_sizes, int n_in,
                              void* d_out, int out_size)
{
    const float* global_feat = (const float*)d_in[0];
    const float* local_feat  = (const float*)d_in[1];
    const float* Wg    = (const float*)d_in[2];
    const float* bg    = (const float*)d_in[3];
    const float* Wl    = (const float*)d_in[4];
    const float* bl    = (const float*)d_in[5];
    const float* ln1_g = (const float*)d_in[6];
    const float* ln1_b = (const float*)d_in[7];
    const float* Wqkv  = (const float*)d_in[8];
    const float* Wo    = (const float*)d_in[9];
    const float* bo    = (const float*)d_in[10];
    const float* ln2_g = (const float*)d_in[11];
    const float* ln2_b = (const float*)d_in[12];
    const float* W1    = (const float*)d_in[13];
    const float* b1    = (const float*)d_in[14];
    const float* W2    = (const float*)d_in[15];
    const float* b2    = (const float*)d_in[16];
    const float* Wq       = (const float*)d_in[17];
    const float* Wk       = (const float*)d_in[18];
    const float* att_bias = (const float*)d_in[19];
    const float* bn_g     = (const float*)d_in[20];
    const float* bn_b     = (const float*)d_in[21];
    const float* bn_mean  = (const float*)d_in[22];
    const float* bn_var   = (const float*)d_in[23];
    const float* Wf       = (const float*)d_in[24];
    const float* bf       = (const float*)d_in[25];

    void *p;
    cudaGetSymbolAddress(&p, g_act);     float* act     = (float*)p;
    cudaGetSymbolAddress(&p, g_qkv);     float* qkv     = (float*)p;
    cudaGetSymbolAddress(&p, g_attnout); float* attnout = (float*)p;
    cudaGetSymbolAddress(&p, g_ff);      float* ff      = (float*)p;
    cudaGetSymbolAddress(&p, g_qh);      float* qh      = (float*)p;
    cudaGetSymbolAddress(&p, g_kh);      float* kh      = (float*)p;
    cudaGetSymbolAddress(&p, g_lpart);   float* lpart   = (float*)p;
    cudaGetSymbolAddress(&p, g_lnstat);  float* lnstat  = (float*)p;
    cudaGetSymbolAddress(&p, g_mask);    int*   mask    = (int*)p;

    float* ga = act;                          // stream 0
    float* la = act + (long long)ROWS * DIM;  // stream 1

    float* out_scalar = (float*)d_out;
    float* scores = out_scalar + BATCH;

    const long long SACT = (long long)ROWS * DIM;
    const long long SQKV = (long long)ROWS * 288;
    const long long SAO  = (long long)ROWS * 96;
    const long long SFF  = (long long)ROWS * 128;
    const long long SLN  = (long long)ROWS * 2;

    // 1) Input projections (ReLU) — different K/W, separate launches
    gemm_tc<1, false, false><<<dim3(3, 128, 1), 256>>>(global_feat, Wg, bg, nullptr, ga,
                                                       nullptr, nullptr, nullptr,
                                                       ROWS, DIM, GD, 0, 0, 0, 0, 1);
    gemm_tc<1, false, false><<<dim3(3, 128, 1), 256>>>(local_feat, Wl, bl, nullptr, la,
                                                       nullptr, nullptr, nullptr,
                                                       ROWS, DIM, LD, 0, 0, 0, 0, 1);

    // 2) Transformer, both streams batched via z=2 (shared weights: sW=0)
    lnstats_k<<<2 * ROWS / 8, 256>>>(act, lnstat);
    gemm_tc<0, false, true><<<dim3(3, 128, 2), 256>>>(act, Wqkv, nullptr, nullptr, qkv,
                                                      lnstat, ln1_g, ln1_b,
                                                      ROWS, 288, 384, SACT, 0, SQKV, SLN, 1);
    flash_attn_k<<<dim3(8, 192), 256>>>(qkv, attnout);
    gemm_tc<0, true, false><<<dim3(3, 128, 2), 256>>>(attnout, Wo, bo, act, act,
                                                      nullptr, nullptr, nullptr,
                                                      ROWS, 384, 96, SAO, 0, SACT, 0, 1);
    lnstats_k<<<2 * ROWS / 8, 256>>>(act, lnstat);
    gemm_tc<2, false, true><<<dim3(1, 128, 2), 256>>>(act, W1, b1, nullptr, ff,
                                                      lnstat, ln2_g, ln2_b,
                                                      ROWS, 128, 384, SACT, 0, SFF, SLN, 1);
    gemm_tc<0, true, false><<<dim3(3, 128, 2), 256>>>(ff, W2, b2, act, act,
                                                      nullptr, nullptr, nullptr,
                                                      ROWS, 384, 128, SFF, 0, SACT, 0, 1);

    // 3) Cross q/k projections
    gemm_tc<0, false, false><<<dim3(3, 128, 1), 256>>>(ga, Wq, nullptr, nullptr, qh,
                                                       nullptr, nullptr, nullptr,
                                                       ROWS, DIM, DIM, 0, 0, 0, 0, 1);
    gemm_tc<0, false, false><<<dim3(3, 128, 1), 256>>>(la, Wk, nullptr, nullptr, kh,
                                                       nullptr, nullptr, nullptr,
                                                       ROWS, DIM, DIM, 0, 0, 0, 0, 1);

    // 4) Mask + cross scores (into d_out)
    mask_k<<<(ROWS * 32 + 255) / 256, 256>>>(global_feat, mask);
    cross_tc<<<dim3(4, 4, 128), 256>>>(qh, kh, att_bias, mask, scores);

    // 5) u-GEMM with fused logits reduction
    ugemm_tc<<<dim3(3, 4, 128), 256>>>(scores, la, ga, lpart);

    // 6) head
    final_k<<<BATCH, 128>>>(lpart, bn_g, bn_b, bn_mean, bn_var, Wf, bf, out_scalar);
}